// round 2
// baseline (speedup 1.0000x reference)
#include <cuda_runtime.h>
#include <math.h>

#define Bc 8
#define Nc 1024
#define Mc 20000
#define Cc 80
#define Gc 64
#define NMS_THRf 0.5f
#define EPSf 1e-6f

#define SETUP_T 256
#define FULL 0xffffffffu

// per-batch results: [b*2+0]=push_b, [b*2+1]=pull_b
__device__ float g_partial[Bc * 2];

__device__ __forceinline__ float iou_legacy(float4 a, float4 b, float area_a, float area_b) {
    float lx = fmaxf(a.x, b.x), ly = fmaxf(a.y, b.y);
    float rx = fminf(a.z, b.z), ry = fminf(a.w, b.w);
    float w = fmaxf(rx - lx + 1.0f, 0.0f), h = fmaxf(ry - ly + 1.0f, 0.0f);
    float ov = w * h;
    return ov / (area_a + area_b - ov);
}

__global__ __launch_bounds__(SETUP_T, 1)
void nms_loss_kernel(const int* __restrict__ pos_inds,
                     const int* __restrict__ pos_gt_index,
                     const float* __restrict__ gt_bboxes,
                     const float* __restrict__ bbox_preds,
                     const float* __restrict__ cls_scores,
                     const int* __restrict__ gt_labels)
{
    const int b = blockIdx.x;
    const int tid = threadIdx.x;

    __shared__ float4 sbox[Nc];
    __shared__ float  sarea[Nc];
    __shared__ float  sscore[Nc];
    __shared__ int    sgt[Nc];
    __shared__ float  sgtiou[Gc * Gc];
    __shared__ int    sseen[Gc];

    // ---- setup (all 256 threads): load boxes, gather scores, gt-gt IoU ----
    const float4* bp = (const float4*)(bbox_preds + (size_t)b * Nc * 4);
    for (int n = tid; n < Nc; n += SETUP_T) {
        float4 bx = bp[n];
        sbox[n] = bx;
        sarea[n] = (bx.z - bx.x + 1.0f) * (bx.w - bx.y + 1.0f);
        int gi = pos_gt_index[b * Nc + n];
        sgt[n] = gi;
        int lbl = gt_labels[b * Gc + gi];
        int pi = pos_inds[b * Nc + n];
        sscore[n] = cls_scores[((size_t)b * Mc + pi) * Cc + lbl];
    }
    const float4* gb = (const float4*)(gt_bboxes + (size_t)b * Gc * 4);
    for (int p = tid; p < Gc * Gc; p += SETUP_T) {
        int g1 = p >> 6, g2 = p & 63;
        float4 a = gb[g1];
        float4 c = gb[g2];
        float a1 = (a.z - a.x + 1.0f) * (a.w - a.y + 1.0f);
        float a2 = (c.z - c.x + 1.0f) * (c.w - c.y + 1.0f);
        sgtiou[p] = iou_legacy(a, c, a1, a2);
    }
    for (int g = tid; g < Gc; g += SETUP_T) sseen[g] = -1;
    __syncthreads();

    if (tid >= 32) return;       // warps 1-7 done; warp 0 runs the scan

    const int lane = tid;
    unsigned amask = FULL;       // alive bits for my 32 items, item n = lane + 32*k

    // initial per-lane local argmax (key = float_bits(score)+1, monotone; dead=0)
    unsigned bestkey = 0u;
    int bestk = 0;
    #pragma unroll
    for (int k = 0; k < 32; k++) {
        unsigned kk = __float_as_uint(sscore[lane + (k << 5)]) + 1u;
        if (kk > bestkey) { bestkey = kk; bestk = k; }
    }

    // lane-0-meaningful accumulators
    float tpull = 0.0f, tpush = 0.0f;
    int pcnt = 0, qcnt = 0;

    for (int step = 0; step < Nc; step++) {
        // ---- argmax (tie -> lowest global index) ----
        unsigned m = __reduce_max_sync(FULL, bestkey);
        if (m == 0u) break;                              // nothing alive
        unsigned myn = (bestkey == m) ? (unsigned)(lane + (bestk << 5)) : 0xffffu;
        int i = (int)__reduce_min_sync(FULL, myn);

        const int g = sgt[i];
        const float4 bi = sbox[i];
        const float ai = sarea[i];

        // ---- pull / seen (all lanes compute; lane 0 holds state) ----
        int prev = sseen[g];
        float pull_term = 0.0f;
        if (prev >= 0) {
            float ms = fmaxf(iou_legacy(sbox[prev], bi, sarea[prev], ai), EPSf);
            pull_term = -__logf(1.0f - NMS_THRf + ms) * sscore[i];
            if (lane == 0) pcnt++;                       // counted even on last pop
        } else {
            sseen[g] = i;                                // all lanes write same value
        }

        // pop i (owner lane clears its bit before the scan)
        bool dirty = false;
        if (lane == (i & 31)) {
            int ki = i >> 5;
            amask &= ~(1u << ki);
            if (ki == bestk) dirty = true;
        }

        // ---- suppression scan over my alive items ----
        float lsum = 0.0f;
        int lnp = 0;
        unsigned mm = amask;
        while (mm) {
            int k = __ffs(mm) - 1;
            mm &= mm - 1;
            int n = lane + (k << 5);
            float4 bn = sbox[n];
            float iouv = iou_legacy(bi, bn, ai, sarea[n]);
            if (iouv > NMS_THRf) {
                amask &= ~(1u << k);
                if (k == bestk) dirty = true;
                int gn = sgt[n];
                if (gn != g && iouv > sgtiou[(g << 6) + gn]) {
                    lnp++;
                    lsum += -__logf(1.0f - iouv) * sscore[n];
                }
            }
        }

        // refresh local argmax only if my best died
        if (dirty) {
            bestkey = 0u; bestk = 0;
            unsigned aa = amask;
            while (aa) {
                int k = __ffs(aa) - 1;
                aa &= aa - 1;
                unsigned kk = __float_as_uint(sscore[lane + (k << 5)]) + 1u;
                if (kk > bestkey) { bestkey = kk; bestk = k; }
            }
        }

        // ---- reductions + accumulate (gated by "remaining") ----
        bool remaining = __ballot_sync(FULL, amask != 0u) != 0u;
        int tnp = __reduce_add_sync(FULL, (unsigned)lnp);
        if (remaining && lane == 0) tpull += pull_term;
        if (tnp > 0) {
            #pragma unroll
            for (int off = 16; off > 0; off >>= 1)
                lsum += __shfl_xor_sync(FULL, lsum, off);
            if (remaining && lane == 0) {
                tpush += lsum / (float)tnp;
                qcnt += tnp;
            }
        }
    }

    if (lane == 0) {
        g_partial[b * 2 + 0] = tpush / ((float)qcnt + EPSf);
        g_partial[b * 2 + 1] = tpull / ((float)pcnt + EPSf);
    }
}

__global__ void finalize_kernel(float* out) {
    float sp = 0.0f, sl = 0.0f;
    for (int b = 0; b < Bc; b++) {
        sp += g_partial[b * 2 + 0];
        sl += g_partial[b * 2 + 1];
    }
    out[0] = sp / (float)Bc;   // mean(push) * PUSH_W
    out[1] = sl / (float)Bc;   // mean(pull) * PULL_W
}

extern "C" void kernel_launch(void* const* d_in, const int* in_sizes, int n_in,
                              void* d_out, int out_size) {
    const int*   pos_inds     = (const int*)d_in[0];
    const int*   pos_gt_index = (const int*)d_in[1];
    const float* gt_bboxes    = (const float*)d_in[2];
    const float* bbox_preds   = (const float*)d_in[3];
    const float* cls_scores   = (const float*)d_in[4];
    const int*   gt_labels    = (const int*)d_in[5];
    float* out = (float*)d_out;

    nms_loss_kernel<<<Bc, SETUP_T>>>(pos_inds, pos_gt_index, gt_bboxes,
                                     bbox_preds, cls_scores, gt_labels);
    finalize_kernel<<<1, 1>>>(out);
}

// round 3
// speedup vs baseline: 8.4188x; 8.4188x over previous
#include <cuda_runtime.h>
#include <math.h>

#define Bc 8
#define Nc 1024
#define Mc 20000
#define Cc 80
#define Gc 64
#define NMS_THRf 0.5f
#define EPSf 1e-6f
#define FULL 0xffffffffu

// per-batch results: [b*2+0]=push_b, [b*2+1]=pull_b
__device__ float g_partial[Bc * 2];
// adjacency bitmasks: per batch, per box, 32 u32 words covering 1024 boxes
__device__ unsigned g_adj[Bc * Nc * 32];

__device__ __forceinline__ float iou_legacy(float4 a, float4 b, float area_a, float area_b) {
    float lx = fmaxf(a.x, b.x), ly = fmaxf(a.y, b.y);
    float rx = fminf(a.z, b.z), ry = fminf(a.w, b.w);
    float w = fmaxf(rx - lx + 1.0f, 0.0f), h = fmaxf(ry - ly + 1.0f, 0.0f);
    float ov = w * h;
    return ov / (area_a + area_b - ov);
}

// ---------------- adjacency precompute: 1 warp per row ----------------
__global__ __launch_bounds__(256)
void adj_kernel(const float* __restrict__ bbox_preds)
{
    __shared__ float4 sb[Nc];
    __shared__ float  sa[Nc];
    const int b = blockIdx.y;
    const float4* bp = (const float4*)(bbox_preds + (size_t)b * Nc * 4);
    for (int n = threadIdx.x; n < Nc; n += 256) {
        float4 bx = bp[n];
        sb[n] = bx;
        sa[n] = (bx.z - bx.x + 1.0f) * (bx.w - bx.y + 1.0f);
    }
    __syncthreads();

    const int wid = threadIdx.x >> 5, lane = threadIdx.x & 31;
    const int i = blockIdx.x * 8 + wid;           // row
    const float4 bi = sb[i];
    const float ai = sa[i];
    unsigned word = 0u;                            // lane k covers items [32k,32k+32)
    #pragma unroll
    for (int j = 0; j < 32; j++) {
        int n = (lane << 5) | j;
        float v = iou_legacy(bi, sb[n], ai, sa[n]);
        if (v > NMS_THRf && n != i) word |= (1u << j);
    }
    g_adj[(((b << 10) + i) << 5) + lane] = word;
}

// ---------------- sequential scan: 1 block per batch ----------------
// dynamic smem layout (bytes):
//   sbox   float4[1024]  @ 0        (16384)
//   sadj   u32[1024*32]  @ 16384    (131072)
//   sgtiou float[64*64]  @ 147456   (16384)
//   sarea  float[1024]   @ 163840   (4096)
//   sscore float[1024]   @ 167936   (4096)
//   sgt    int[1024]     @ 172032   (4096)
//   sseen  int[64]       @ 176128   (256)
#define SMEM_BYTES 176384

extern __shared__ unsigned char smem_raw[];

__global__ __launch_bounds__(256, 1)
void nms_loss_kernel(const int* __restrict__ pos_inds,
                     const int* __restrict__ pos_gt_index,
                     const float* __restrict__ gt_bboxes,
                     const float* __restrict__ cls_scores,
                     const int* __restrict__ gt_labels,
                     const float* __restrict__ bbox_preds)
{
    float4*   sbox   = (float4*)(smem_raw);
    unsigned* sadj   = (unsigned*)(smem_raw + 16384);
    float*    sgtiou = (float*)(smem_raw + 147456);
    float*    sarea  = (float*)(smem_raw + 163840);
    float*    sscore = (float*)(smem_raw + 167936);
    int*      sgt    = (int*)(smem_raw + 172032);
    int*      sseen  = (int*)(smem_raw + 176128);

    const int b = blockIdx.x;
    const int tid = threadIdx.x;

    // ---- setup (256 threads) ----
    const float4* bp = (const float4*)(bbox_preds + (size_t)b * Nc * 4);
    for (int n = tid; n < Nc; n += 256) {
        float4 bx = bp[n];
        sbox[n] = bx;
        sarea[n] = (bx.z - bx.x + 1.0f) * (bx.w - bx.y + 1.0f);
        int gi = pos_gt_index[b * Nc + n];
        sgt[n] = gi;
        int lbl = gt_labels[b * Gc + gi];
        int pi = pos_inds[b * Nc + n];
        sscore[n] = cls_scores[((size_t)b * Mc + pi) * Cc + lbl];
    }
    const float4* gb = (const float4*)(gt_bboxes + (size_t)b * Gc * 4);
    for (int p = tid; p < Gc * Gc; p += 256) {
        int g1 = p >> 6, g2 = p & 63;
        float4 a = gb[g1];
        float4 c = gb[g2];
        float a1 = (a.z - a.x + 1.0f) * (a.w - a.y + 1.0f);
        float a2 = (c.z - c.x + 1.0f) * (c.w - c.y + 1.0f);
        sgtiou[p] = iou_legacy(a, c, a1, a2);
    }
    for (int g = tid; g < Gc; g += 256) sseen[g] = -1;
    // copy this batch's adjacency (128KB) into smem
    {
        const uint4* asrc = (const uint4*)(g_adj + ((size_t)b << 15));
        uint4* adst = (uint4*)sadj;
        for (int p = tid; p < (Nc * 32 / 4); p += 256) adst[p] = asrc[p];
    }
    __syncthreads();

    if (tid >= 32) return;     // warp 0 runs the scan
    const int lane = tid;

    // register score-key cache for my 32 items (key = float_bits+1; monotone, >0)
    unsigned skey[32];
    #pragma unroll
    for (int k = 0; k < 32; k++) skey[k] = __float_as_uint(sscore[(lane << 5) | k]) + 1u;

    unsigned aword = FULL;     // alive bits for items [lane*32, lane*32+32)
    unsigned bestkey = 0u;
    int bestk = 0;
    #pragma unroll
    for (int k = 0; k < 32; k++) {
        if (skey[k] > bestkey) { bestkey = skey[k]; bestk = k; }
    }

    float tpull = 0.0f, tpush = 0.0f;
    int pcnt = 0, qcnt = 0;

    for (int step = 0; step < Nc; step++) {
        // ---- argmax (tie -> lowest global index) ----
        unsigned m = __reduce_max_sync(FULL, bestkey);
        if (m == 0u) break;
        int i = (int)__reduce_min_sync(FULL,
                    (bestkey == m) ? (unsigned)((lane << 5) | bestk) : 0xffffu);

        const int g = sgt[i];
        const float4 bi = sbox[i];
        const float ai = sarea[i];

        // pop i (owner lane); popped item is always its owner's local best
        bool dirty = false;
        if (lane == (i >> 5)) { aword &= ~(1u << (i & 31)); dirty = true; }

        // "remaining" snapshot: after popping i, BEFORE suppression kills
        unsigned aliveflag = (aword != 0u) ? 0x10000u : 0u;

        // ---- pull / seen (uniform across warp) ----
        int prev = sseen[g];
        float pull_term = 0.0f;
        if (prev >= 0) {
            float ms = fmaxf(iou_legacy(sbox[prev], bi, sarea[prev], ai), EPSf);
            pull_term = -__logf(1.0f - NMS_THRf + ms) * sscore[i];
            if (lane == 0) pcnt++;               // counted even on last pop
        } else {
            sseen[g] = i;                        // all lanes write same value
        }

        // ---- suppression via adjacency word ----
        unsigned w = sadj[(i << 5) + lane] & aword;
        float lsum = 0.0f;
        int lnp = 0;
        if (w) {
            aword &= ~w;
            if (bestkey && ((w >> bestk) & 1u)) dirty = true;
            unsigned ww = w;
            do {
                int k = __ffs(ww) - 1;
                ww &= ww - 1;
                int n = (lane << 5) | k;
                int gn = sgt[n];
                if (gn != g) {
                    float iouv = iou_legacy(bi, sbox[n], ai, sarea[n]);
                    if (iouv > sgtiou[(g << 6) + gn]) {
                        lnp++;
                        lsum += -__logf(1.0f - iouv) * sscore[n];
                    }
                }
            } while (ww);
        }

        // refresh local argmax from registers (fully unrolled, static indices)
        if (dirty) {
            bestkey = 0u; bestk = 0;
            #pragma unroll
            for (int k = 0; k < 32; k++) {
                unsigned kk = ((aword >> k) & 1u) ? skey[k] : 0u;
                if (kk > bestkey) { bestkey = kk; bestk = k; }
            }
        }

        // ---- packed reduction: push count + remaining flag ----
        unsigned red = __reduce_add_sync(FULL, (unsigned)lnp + aliveflag);
        int tnp = (int)(red & 0xffffu);
        bool remaining = (red >> 16) != 0u;

        if (remaining && lane == 0) tpull += pull_term;
        if (tnp > 0) {
            #pragma unroll
            for (int off = 16; off > 0; off >>= 1)
                lsum += __shfl_xor_sync(FULL, lsum, off);
            if (remaining && lane == 0) {
                tpush += lsum / (float)tnp;
                qcnt += tnp;
            }
        }
    }

    if (lane == 0) {
        g_partial[b * 2 + 0] = tpush / ((float)qcnt + EPSf);
        g_partial[b * 2 + 1] = tpull / ((float)pcnt + EPSf);
    }
}

__global__ void finalize_kernel(float* out) {
    float sp = 0.0f, sl = 0.0f;
    for (int b = 0; b < Bc; b++) {
        sp += g_partial[b * 2 + 0];
        sl += g_partial[b * 2 + 1];
    }
    out[0] = sp / (float)Bc;   // mean(push) * PUSH_W
    out[1] = sl / (float)Bc;   // mean(pull) * PULL_W
}

extern "C" void kernel_launch(void* const* d_in, const int* in_sizes, int n_in,
                              void* d_out, int out_size) {
    const int*   pos_inds     = (const int*)d_in[0];
    const int*   pos_gt_index = (const int*)d_in[1];
    const float* gt_bboxes    = (const float*)d_in[2];
    const float* bbox_preds   = (const float*)d_in[3];
    const float* cls_scores   = (const float*)d_in[4];
    const int*   gt_labels    = (const int*)d_in[5];
    float* out = (float*)d_out;

    static int attr_set = 0;
    if (!attr_set) {
        cudaFuncSetAttribute(nms_loss_kernel,
                             cudaFuncAttributeMaxDynamicSharedMemorySize, SMEM_BYTES);
        attr_set = 1;
    }

    adj_kernel<<<dim3(128, 8), 256>>>(bbox_preds);
    nms_loss_kernel<<<Bc, 256, SMEM_BYTES>>>(pos_inds, pos_gt_index, gt_bboxes,
                                             cls_scores, gt_labels, bbox_preds);
    finalize_kernel<<<1, 1>>>(out);
}

// round 4
// speedup vs baseline: 13.2006x; 1.5680x over previous
#include <cuda_runtime.h>
#include <math.h>

#define Bc 8
#define Nc 1024
#define Mc 20000
#define Cc 80
#define Gc 64
#define NMS_THRf 0.5f
#define EPSf 1e-6f
#define FULL 0xffffffffu

// per-batch results: [b*2+0]=push_b, [b*2+1]=pull_b
__device__ float g_partial[Bc * 2];
// adjacency bitmasks in RANK space: row r, word L, bit s covers rank (s<<5)|L
__device__ unsigned g_adj[Bc * Nc * 32];
// gathered scores (original index space)
__device__ float g_scores[Bc * Nc];
// permutation: g_perm[b][rank] = original index
__device__ int g_perm[Bc * Nc];

__device__ __forceinline__ float iou_legacy(float4 a, float4 b, float area_a, float area_b) {
    float lx = fmaxf(a.x, b.x), ly = fmaxf(a.y, b.y);
    float rx = fminf(a.z, b.z), ry = fminf(a.w, b.w);
    float w = fmaxf(rx - lx + 1.0f, 0.0f), h = fmaxf(ry - ly + 1.0f, 0.0f);
    float ov = w * h;
    return ov / (area_a + area_b - ov);
}

// ---------------- score gather ----------------
__global__ __launch_bounds__(256)
void gather_kernel(const int* __restrict__ pos_inds,
                   const int* __restrict__ pos_gt_index,
                   const float* __restrict__ cls_scores,
                   const int* __restrict__ gt_labels)
{
    const int b = blockIdx.x;
    for (int n = threadIdx.x; n < Nc; n += 256) {
        int gi = pos_gt_index[b * Nc + n];
        int lbl = gt_labels[b * Gc + gi];
        int pi = pos_inds[b * Nc + n];
        g_scores[(b << 10) + n] = cls_scores[((size_t)b * Mc + pi) * Cc + lbl];
    }
}

// ---------------- rank computation: 1 warp per row ----------------
__global__ __launch_bounds__(256)
void rank_kernel(void)
{
    __shared__ float ssc[Nc];
    const int b = blockIdx.y;
    for (int n = threadIdx.x; n < Nc; n += 256)
        ssc[n] = g_scores[(b << 10) + n];
    __syncthreads();

    const int wid = threadIdx.x >> 5, lane = threadIdx.x & 31;
    const int i = blockIdx.x * 8 + wid;
    const float si = ssc[i];
    int cnt = 0;
    #pragma unroll
    for (int w = 0; w < 32; w++) {
        int n = (w << 5) | lane;            // coalesced, conflict-free
        float sn = ssc[n];
        cnt += (sn > si) || (sn == si && n < i);
    }
    cnt = __reduce_add_sync(FULL, cnt);
    if (lane == 0) g_perm[(b << 10) + cnt] = i;   // unique ranks -> no conflicts
}

// ---------------- adjacency in rank space: 1 warp per row ----------------
__global__ __launch_bounds__(256)
void adj_kernel(const float* __restrict__ bbox_preds)
{
    __shared__ float4 sb[Nc];
    __shared__ float  sa[Nc];
    const int b = blockIdx.y;
    const float4* bp = (const float4*)(bbox_preds + (size_t)b * Nc * 4);
    for (int n = threadIdx.x; n < Nc; n += 256) {
        int orig = g_perm[(b << 10) + n];
        float4 bx = bp[orig];
        sb[n] = bx;
        sa[n] = (bx.z - bx.x + 1.0f) * (bx.w - bx.y + 1.0f);
    }
    __syncthreads();

    const int wid = threadIdx.x >> 5, lane = threadIdx.x & 31;
    const int i = blockIdx.x * 8 + wid;     // rank-space row
    const float4 bi = sb[i];
    const float ai = sa[i];
    unsigned myword = 0u;
    #pragma unroll
    for (int w = 0; w < 32; w++) {
        int n = (w << 5) | lane;            // coalesced, conflict-free
        float v = iou_legacy(bi, sb[n], ai, sa[n]);
        unsigned bal = __ballot_sync(FULL, v > NMS_THRf && n != i);
        myword |= ((bal >> lane) & 1u) << w;   // transpose: my bit w covers (w<<5)|lane
    }
    g_adj[(((b << 10) + i) << 5) + lane] = myword;
}

// ---------------- sequential scan: 1 block per batch ----------------
// dynamic smem layout (bytes):
//   sboxA  float4[1024] @ 0       box coords                (16384)
//   sboxB  float4[1024] @ 16384   (area, score, gt, -)      (16384)
//   sadj   u32[1024*32] @ 32768                             (131072)
//   sgtiou float[64*64] @ 163840                            (16384)
//   sseen  int[64]      @ 180224                            (256)
#define SMEM_BYTES 180480

extern __shared__ unsigned char smem_raw[];

__global__ __launch_bounds__(256, 1)
void nms_loss_kernel(const int* __restrict__ pos_gt_index,
                     const float* __restrict__ gt_bboxes,
                     const float* __restrict__ bbox_preds)
{
    float4*   sboxA  = (float4*)(smem_raw);
    float4*   sboxB  = (float4*)(smem_raw + 16384);
    unsigned* sadj   = (unsigned*)(smem_raw + 32768);
    float*    sgtiou = (float*)(smem_raw + 163840);
    int*      sseen  = (int*)(smem_raw + 180224);

    const int b = blockIdx.x;
    const int tid = threadIdx.x;

    // ---- setup (256 threads): permuted arrays by rank ----
    const float4* bp = (const float4*)(bbox_preds + (size_t)b * Nc * 4);
    for (int r = tid; r < Nc; r += 256) {
        int orig = g_perm[(b << 10) + r];
        float4 bx = bp[orig];
        sboxA[r] = bx;
        float area = (bx.z - bx.x + 1.0f) * (bx.w - bx.y + 1.0f);
        float sc = g_scores[(b << 10) + orig];
        int gi = pos_gt_index[b * Nc + orig];
        sboxB[r] = make_float4(area, sc, __int_as_float(gi), 0.0f);
    }
    const float4* gb = (const float4*)(gt_bboxes + (size_t)b * Gc * 4);
    for (int p = tid; p < Gc * Gc; p += 256) {
        int g1 = p >> 6, g2 = p & 63;
        float4 a = gb[g1];
        float4 c = gb[g2];
        float a1 = (a.z - a.x + 1.0f) * (a.w - a.y + 1.0f);
        float a2 = (c.z - c.x + 1.0f) * (c.w - c.y + 1.0f);
        sgtiou[p] = iou_legacy(a, c, a1, a2);
    }
    for (int g = tid; g < Gc; g += 256) sseen[g] = -1;
    {
        const uint4* asrc = (const uint4*)(g_adj + ((size_t)b << 15));
        uint4* adst = (uint4*)sadj;
        for (int p = tid; p < (Nc * 32 / 4); p += 256) adst[p] = asrc[p];
    }
    __syncthreads();

    if (tid >= 32) return;       // warp 0 runs the scan
    const int lane = tid;

    unsigned aword = FULL;       // alive bits: bit s covers rank (s<<5)|lane
    float tpull = 0.0f, tpush = 0.0f;
    int pcnt = 0, qcnt = 0;

    while (true) {
        // ---- pop = min alive rank: ffs + one reduce_min ----
        unsigned cand = aword ? ((unsigned)(__ffs(aword) - 1) << 5) | (unsigned)lane
                              : 0xffffffffu;
        unsigned r = __reduce_min_sync(FULL, cand);
        if (r == 0xffffffffu) break;

        const float4 bA = sboxA[r];
        const float4 bB = sboxB[r];
        const float ai = bB.x;
        const float si = bB.y;
        const int g = __float_as_int(bB.z);

        // pop i (owner lane clears bit), then snapshot "remaining"
        if (lane == (int)(r & 31u)) aword &= ~(1u << (r >> 5));
        unsigned aliveflag = (aword != 0u) ? 0x10000u : 0u;

        // ---- pull / seen (uniform across warp) ----
        int prev = sseen[g];
        float pull_term = 0.0f;
        if (prev >= 0) {
            float pa = sboxB[prev].x;
            float ms = fmaxf(iou_legacy(sboxA[prev], bA, pa, ai), EPSf);
            pull_term = -__logf(1.0f - NMS_THRf + ms) * si;
            if (lane == 0) pcnt++;           // counted even on last pop
        } else {
            sseen[g] = (int)r;               // all lanes write same value
        }

        // ---- suppression via adjacency word ----
        unsigned wv = sadj[((int)r << 5) + lane] & aword;
        float lsum = 0.0f;
        int lnp = 0;
        if (wv) {
            aword &= ~wv;
            unsigned ww = wv;
            do {
                int s = __ffs(ww) - 1;
                ww &= ww - 1;
                int n = (s << 5) | lane;
                float4 nB = sboxB[n];
                int gn = __float_as_int(nB.z);
                if (gn != g) {
                    float iouv = iou_legacy(bA, sboxA[n], ai, nB.x);
                    if (iouv > sgtiou[(g << 6) + gn]) {
                        lnp++;
                        lsum += -__logf(1.0f - iouv) * nB.y;
                    }
                }
            } while (ww);
        }

        // ---- packed reduction: push count + remaining flag ----
        unsigned red = __reduce_add_sync(FULL, (unsigned)lnp + aliveflag);
        int tnp = (int)(red & 0xffffu);
        bool remaining = (red >> 16) != 0u;

        if (remaining && lane == 0) tpull += pull_term;
        if (tnp > 0) {
            #pragma unroll
            for (int off = 16; off > 0; off >>= 1)
                lsum += __shfl_xor_sync(FULL, lsum, off);
            if (remaining && lane == 0) {
                tpush += lsum / (float)tnp;
                qcnt += tnp;
            }
        }
    }

    if (lane == 0) {
        g_partial[b * 2 + 0] = tpush / ((float)qcnt + EPSf);
        g_partial[b * 2 + 1] = tpull / ((float)pcnt + EPSf);
    }
}

__global__ void finalize_kernel(float* out) {
    float sp = 0.0f, sl = 0.0f;
    for (int b = 0; b < Bc; b++) {
        sp += g_partial[b * 2 + 0];
        sl += g_partial[b * 2 + 1];
    }
    out[0] = sp / (float)Bc;   // mean(push) * PUSH_W
    out[1] = sl / (float)Bc;   // mean(pull) * PULL_W
}

extern "C" void kernel_launch(void* const* d_in, const int* in_sizes, int n_in,
                              void* d_out, int out_size) {
    const int*   pos_inds     = (const int*)d_in[0];
    const int*   pos_gt_index = (const int*)d_in[1];
    const float* gt_bboxes    = (const float*)d_in[2];
    const float* bbox_preds   = (const float*)d_in[3];
    const float* cls_scores   = (const float*)d_in[4];
    const int*   gt_labels    = (const int*)d_in[5];
    float* out = (float*)d_out;

    cudaFuncSetAttribute(nms_loss_kernel,
                         cudaFuncAttributeMaxDynamicSharedMemorySize, SMEM_BYTES);

    gather_kernel<<<Bc, 256>>>(pos_inds, pos_gt_index, cls_scores, gt_labels);
    rank_kernel<<<dim3(128, Bc), 256>>>();
    adj_kernel<<<dim3(128, Bc), 256>>>(bbox_preds);
    nms_loss_kernel<<<Bc, 256, SMEM_BYTES>>>(pos_gt_index, gt_bboxes, bbox_preds);
    finalize_kernel<<<1, 1>>>(out);
}

// round 5
// speedup vs baseline: 40.5568x; 3.0724x over previous
#include <cuda_runtime.h>
#include <math.h>

#define Bc 8
#define Nc 1024
#define Mc 20000
#define Cc 80
#define Gc 64
#define NMS_THRf 0.5f
#define EPSf 1e-6f
#define FULL 0xffffffffu

// per-batch results: [b*2+0]=push_b, [b*2+1]=pull_b
__device__ float g_partial[Bc * 2];
// adjacency bitmasks in RANK space: row r, word L, bit s <-> rank (L<<5)|s
__device__ unsigned g_adj[Bc * Nc * 32];
// gathered scores (original index space)
__device__ float g_scores[Bc * Nc];
// permutation: g_perm[b][rank] = original index
__device__ int g_perm[Bc * Nc];

__device__ __forceinline__ float iou_legacy(float4 a, float4 b, float area_a, float area_b) {
    float lx = fmaxf(a.x, b.x), ly = fmaxf(a.y, b.y);
    float rx = fminf(a.z, b.z), ry = fminf(a.w, b.w);
    float w = fmaxf(rx - lx + 1.0f, 0.0f), h = fmaxf(ry - ly + 1.0f, 0.0f);
    float ov = w * h;
    return ov / (area_a + area_b - ov);
}

// ---------------- score gather ----------------
__global__ __launch_bounds__(256)
void gather_kernel(const int* __restrict__ pos_inds,
                   const int* __restrict__ pos_gt_index,
                   const float* __restrict__ cls_scores,
                   const int* __restrict__ gt_labels)
{
    const int b = blockIdx.x;
    for (int n = threadIdx.x; n < Nc; n += 256) {
        int gi = pos_gt_index[b * Nc + n];
        int lbl = gt_labels[b * Gc + gi];
        int pi = pos_inds[b * Nc + n];
        g_scores[(b << 10) + n] = cls_scores[((size_t)b * Mc + pi) * Cc + lbl];
    }
}

// ---------------- rank computation: 1 warp per row ----------------
__global__ __launch_bounds__(256)
void rank_kernel(void)
{
    __shared__ float ssc[Nc];
    const int b = blockIdx.y;
    for (int n = threadIdx.x; n < Nc; n += 256)
        ssc[n] = g_scores[(b << 10) + n];
    __syncthreads();

    const int wid = threadIdx.x >> 5, lane = threadIdx.x & 31;
    const int i = blockIdx.x * 8 + wid;
    const float si = ssc[i];
    int cnt = 0;
    #pragma unroll
    for (int w = 0; w < 32; w++) {
        int n = (w << 5) | lane;            // coalesced, conflict-free
        float sn = ssc[n];
        cnt += (sn > si) || (sn == si && n < i);
    }
    cnt = __reduce_add_sync(FULL, cnt);
    if (lane == 0) g_perm[(b << 10) + cnt] = i;   // unique ranks -> no conflicts
}

// ---------------- adjacency in rank space: 1 warp per row ----------------
__global__ __launch_bounds__(256)
void adj_kernel(const float* __restrict__ bbox_preds)
{
    __shared__ float4 sb[Nc];
    __shared__ float  sa[Nc];
    const int b = blockIdx.y;
    const float4* bp = (const float4*)(bbox_preds + (size_t)b * Nc * 4);
    for (int n = threadIdx.x; n < Nc; n += 256) {
        int orig = g_perm[(b << 10) + n];
        float4 bx = bp[orig];
        sb[n] = bx;
        sa[n] = (bx.z - bx.x + 1.0f) * (bx.w - bx.y + 1.0f);
    }
    __syncthreads();

    const int wid = threadIdx.x >> 5, lane = threadIdx.x & 31;
    const int i = blockIdx.x * 8 + wid;     // rank-space row
    const float4 bi = sb[i];
    const float ai = sa[i];
    unsigned myword = 0u;
    #pragma unroll
    for (int w = 0; w < 32; w++) {
        int n = (w << 5) | lane;            // coalesced, conflict-free
        float v = iou_legacy(bi, sb[n], ai, sa[n]);
        unsigned bal = __ballot_sync(FULL, v > NMS_THRf && n != i);
        if (w == lane) myword = bal;        // word L bit s <-> rank (L<<5)|s
    }
    g_adj[(((b << 10) + i) << 5) + lane] = myword;
}

// ---------------- fixpoint + parallel loss: 1 block per batch ----------------
// dynamic smem layout (bytes):
//   sboxA   float4[1024] @ 0       box coords                (16384)
//   sboxB   float4[1024] @ 16384   (area, score, gt, -)      (16384)
//   sadj    u32[1024*32] @ 32768                             (131072)
//   sgtiou  float[64*64] @ 163840                            (16384)
//   skiller int[1024]    @ 180224                            (4096)
//   snpush  int[1024]    @ 184320                            (4096)
//   sfirst  int[64]      @ 188416                            (256)
#define SMEM_BYTES 188672

extern __shared__ unsigned char smem_raw[];

__global__ __launch_bounds__(256, 1)
void nms_loss_kernel(const int* __restrict__ pos_gt_index,
                     const float* __restrict__ gt_bboxes,
                     const float* __restrict__ bbox_preds)
{
    float4*   sboxA   = (float4*)(smem_raw);
    float4*   sboxB   = (float4*)(smem_raw + 16384);
    unsigned* sadj    = (unsigned*)(smem_raw + 32768);
    float*    sgtiou  = (float*)(smem_raw + 163840);
    int*      skiller = (int*)(smem_raw + 180224);
    int*      snpush  = (int*)(smem_raw + 184320);
    int*      sfirst  = (int*)(smem_raw + 188416);

    __shared__ int   s_lastr;
    __shared__ float s_pull, s_push;
    __shared__ int   s_pcnt, s_qcnt;

    const int b = blockIdx.x;
    const int tid = threadIdx.x;

    // ---- setup (256 threads): permuted arrays by rank ----
    const float4* bp = (const float4*)(bbox_preds + (size_t)b * Nc * 4);
    for (int r = tid; r < Nc; r += 256) {
        int orig = g_perm[(b << 10) + r];
        float4 bx = bp[orig];
        sboxA[r] = bx;
        float area = (bx.z - bx.x + 1.0f) * (bx.w - bx.y + 1.0f);
        float sc = g_scores[(b << 10) + orig];
        int gi = pos_gt_index[b * Nc + orig];
        sboxB[r] = make_float4(area, sc, __int_as_float(gi), 0.0f);
        skiller[r] = -1;
        snpush[r] = 0;
    }
    const float4* gb = (const float4*)(gt_bboxes + (size_t)b * Gc * 4);
    for (int p = tid; p < Gc * Gc; p += 256) {
        int g1 = p >> 6, g2 = p & 63;
        float4 a = gb[g1];
        float4 c = gb[g2];
        float a1 = (a.z - a.x + 1.0f) * (a.w - a.y + 1.0f);
        float a2 = (c.z - c.x + 1.0f) * (c.w - c.y + 1.0f);
        sgtiou[p] = iou_legacy(a, c, a1, a2);
    }
    for (int g = tid; g < Gc; g += 256) sfirst[g] = 1 << 30;
    {
        const uint4* asrc = (const uint4*)(g_adj + ((size_t)b << 15));
        uint4* adst = (uint4*)sadj;
        for (int p = tid; p < (Nc * 32 / 4); p += 256) adst[p] = asrc[p];
    }
    if (tid == 0) { s_pull = 0.0f; s_push = 0.0f; s_pcnt = 0; s_qcnt = 0; }
    __syncthreads();

    // ---- Phase 1: bitwise NMS fixpoint (warp 0 only) ----
    if (tid < 32) {
        const int lane = tid;
        unsigned aword = FULL;          // bit s <-> rank (lane<<5)|s
        int lastr = 0;
        while (true) {
            unsigned cand = aword ? (unsigned)((lane << 5) | (__ffs(aword) - 1))
                                  : 0xffffu;
            unsigned r = __reduce_min_sync(FULL, cand);
            if (r == 0xffffu) break;
            lastr = (int)r;
            if (lane == (int)(r >> 5)) aword &= ~(1u << (r & 31u));
            unsigned kv = sadj[((int)r << 5) + lane] & aword;
            if (kv) {
                aword &= ~kv;
                unsigned t = kv;
                do {
                    int s = __ffs(t) - 1;
                    t &= t - 1;
                    skiller[(lane << 5) | s] = (int)r;
                } while (t);
            }
        }
        if (lane == 0) s_lastr = lastr;
    }
    __syncthreads();

    const int lastr = s_lastr;

    // ---- Phase 2a: first-kept-per-gt, push histogram, last-step liveness ----
    int pred_last = 0;
    for (int n = tid; n < Nc; n += 256) {
        int kr = skiller[n];
        if (kr < 0) {
            int g = __float_as_int(sboxB[n].z);
            atomicMin(&sfirst[g], n);
        } else {
            if (kr == lastr) pred_last = 1;
            int g = __float_as_int(sboxB[kr].z);
            int gn = __float_as_int(sboxB[n].z);
            if (gn != g) {
                float iouv = iou_legacy(sboxA[kr], sboxA[n], sboxB[kr].x, sboxB[n].x);
                if (iouv > sgtiou[(g << 6) + gn]) atomicAdd(&snpush[kr], 1);
            }
        }
    }
    int last_rem = __syncthreads_or(pred_last);   // barrier + OR

    // ---- Phase 2b: accumulate pull/push in parallel ----
    float lpull = 0.0f, lpush = 0.0f;
    int lpc = 0, lqc = 0;
    for (int n = tid; n < Nc; n += 256) {
        int kr = skiller[n];
        if (kr < 0) {
            int g = __float_as_int(sboxB[n].z);
            int prev = sfirst[g];
            if (prev < n) {
                lpc++;                                     // pcnt is ungated
                if (!(n == lastr && !last_rem)) {
                    float ms = fmaxf(iou_legacy(sboxA[prev], sboxA[n],
                                                sboxB[prev].x, sboxB[n].x), EPSf);
                    lpull += -__logf(1.0f - NMS_THRf + ms) * sboxB[n].y;
                }
            }
        } else {
            int g = __float_as_int(sboxB[kr].z);
            int gn = __float_as_int(sboxB[n].z);
            if (gn != g) {
                float iouv = iou_legacy(sboxA[kr], sboxA[n], sboxB[kr].x, sboxB[n].x);
                if (iouv > sgtiou[(g << 6) + gn]) {
                    lqc++;
                    lpush += -__logf(1.0f - iouv) * sboxB[n].y / (float)snpush[kr];
                }
            }
        }
    }
    // warp-level reduce then shared atomics (8 warps)
    #pragma unroll
    for (int off = 16; off > 0; off >>= 1) {
        lpull += __shfl_xor_sync(FULL, lpull, off);
        lpush += __shfl_xor_sync(FULL, lpush, off);
        lpc   += __shfl_xor_sync(FULL, lpc, off);
        lqc   += __shfl_xor_sync(FULL, lqc, off);
    }
    if ((tid & 31) == 0) {
        atomicAdd(&s_pull, lpull);
        atomicAdd(&s_push, lpush);
        atomicAdd(&s_pcnt, lpc);
        atomicAdd(&s_qcnt, lqc);
    }
    __syncthreads();

    if (tid == 0) {
        g_partial[b * 2 + 0] = s_push / ((float)s_qcnt + EPSf);
        g_partial[b * 2 + 1] = s_pull / ((float)s_pcnt + EPSf);
    }
}

__global__ void finalize_kernel(float* out) {
    float sp = 0.0f, sl = 0.0f;
    for (int b = 0; b < Bc; b++) {
        sp += g_partial[b * 2 + 0];
        sl += g_partial[b * 2 + 1];
    }
    out[0] = sp / (float)Bc;   // mean(push) * PUSH_W
    out[1] = sl / (float)Bc;   // mean(pull) * PULL_W
}

extern "C" void kernel_launch(void* const* d_in, const int* in_sizes, int n_in,
                              void* d_out, int out_size) {
    const int*   pos_inds     = (const int*)d_in[0];
    const int*   pos_gt_index = (const int*)d_in[1];
    const float* gt_bboxes    = (const float*)d_in[2];
    const float* bbox_preds   = (const float*)d_in[3];
    const float* cls_scores   = (const float*)d_in[4];
    const int*   gt_labels    = (const int*)d_in[5];
    float* out = (float*)d_out;

    cudaFuncSetAttribute(nms_loss_kernel,
                         cudaFuncAttributeMaxDynamicSharedMemorySize, SMEM_BYTES);

    gather_kernel<<<Bc, 256>>>(pos_inds, pos_gt_index, cls_scores, gt_labels);
    rank_kernel<<<dim3(128, Bc), 256>>>();
    adj_kernel<<<dim3(128, Bc), 256>>>(bbox_preds);
    nms_loss_kernel<<<Bc, 256, SMEM_BYTES>>>(pos_gt_index, gt_bboxes, bbox_preds);
    finalize_kernel<<<1, 1>>>(out);
}

// round 6
// speedup vs baseline: 47.6790x; 1.1756x over previous
#include <cuda_runtime.h>
#include <math.h>

#define Bc 8
#define Nc 1024
#define Mc 20000
#define Cc 80
#define Gc 64
#define NMS_THRf 0.5f
#define EPSf 1e-6f
#define FULL 0xffffffffu

// per-batch results: [b*2+0]=push_b, [b*2+1]=pull_b
__device__ float g_partial[Bc * 2];
__device__ int   g_done;
// adjacency bitmasks in RANK space: row r, word L, bit s <-> rank (L<<5)|s
__device__ unsigned g_adj[Bc * Nc * 32];
// gathered scores (original index space)
__device__ float g_scores[Bc * Nc];
// permutation: g_perm[b][rank] = original index
__device__ int g_perm[Bc * Nc];

__device__ __forceinline__ float iou_legacy(float4 a, float4 b, float area_a, float area_b) {
    float lx = fmaxf(a.x, b.x), ly = fmaxf(a.y, b.y);
    float rx = fminf(a.z, b.z), ry = fminf(a.w, b.w);
    float w = fmaxf(rx - lx + 1.0f, 0.0f), h = fmaxf(ry - ly + 1.0f, 0.0f);
    float ov = w * h;
    return ov / (area_a + area_b - ov);
}

// ---------------- score gather (also resets completion counter) ----------------
__global__ __launch_bounds__(256)
void gather_kernel(const int* __restrict__ pos_inds,
                   const int* __restrict__ pos_gt_index,
                   const float* __restrict__ cls_scores,
                   const int* __restrict__ gt_labels)
{
    const int b = blockIdx.x;
    if (b == 0 && threadIdx.x == 0) g_done = 0;
    for (int n = threadIdx.x; n < Nc; n += 256) {
        int gi = pos_gt_index[b * Nc + n];
        int lbl = gt_labels[b * Gc + gi];
        int pi = pos_inds[b * Nc + n];
        g_scores[(b << 10) + n] = cls_scores[((size_t)b * Mc + pi) * Cc + lbl];
    }
}

// ---------------- rank computation: 1 warp per row ----------------
__global__ __launch_bounds__(256)
void rank_kernel(void)
{
    __shared__ float ssc[Nc];
    const int b = blockIdx.y;
    for (int n = threadIdx.x; n < Nc; n += 256)
        ssc[n] = g_scores[(b << 10) + n];
    __syncthreads();

    const int wid = threadIdx.x >> 5, lane = threadIdx.x & 31;
    const int i = blockIdx.x * 8 + wid;
    const float si = ssc[i];
    int cnt = 0;
    #pragma unroll
    for (int w = 0; w < 32; w++) {
        int n = (w << 5) | lane;            // coalesced, conflict-free
        float sn = ssc[n];
        cnt += (sn > si) || (sn == si && n < i);
    }
    cnt = __reduce_add_sync(FULL, cnt);
    if (lane == 0) g_perm[(b << 10) + cnt] = i;   // unique ranks -> no conflicts
}

// ---------------- adjacency in rank space: 1 warp per row ----------------
__global__ __launch_bounds__(256)
void adj_kernel(const float* __restrict__ bbox_preds)
{
    __shared__ float4 sb[Nc];
    __shared__ float  sa[Nc];
    const int b = blockIdx.y;
    const float4* bp = (const float4*)(bbox_preds + (size_t)b * Nc * 4);
    for (int n = threadIdx.x; n < Nc; n += 256) {
        int orig = g_perm[(b << 10) + n];
        float4 bx = bp[orig];
        sb[n] = bx;
        sa[n] = (bx.z - bx.x + 1.0f) * (bx.w - bx.y + 1.0f);
    }
    __syncthreads();

    const int wid = threadIdx.x >> 5, lane = threadIdx.x & 31;
    const int i = blockIdx.x * 8 + wid;     // rank-space row
    const float4 bi = sb[i];
    const float ai = sa[i];
    unsigned myword = 0u;
    #pragma unroll
    for (int w = 0; w < 32; w++) {
        int n = (w << 5) | lane;            // coalesced, conflict-free
        float v = iou_legacy(bi, sb[n], ai, sa[n]);
        unsigned bal = __ballot_sync(FULL, v > NMS_THRf && n != i);
        if (w == lane) myword = bal;        // word L bit s <-> rank (L<<5)|s
    }
    g_adj[(((b << 10) + i) << 5) + lane] = myword;
}

// ---------------- fixpoint + parallel loss: 1 block per batch ----------------
// dynamic smem layout (bytes):
//   sboxA   float4[1024] @ 0       box coords                (16384)
//   sboxB   float4[1024] @ 16384   (area, score, gt, -)      (16384)
//   sadj    u32[1024*32] @ 32768                             (131072)
//   sgtiou  float[64*64] @ 163840                            (16384)
//   skiller int[1024]    @ 180224                            (4096)
//   snpush  int[1024]    @ 184320                            (4096)
//   sfirst  int[64]      @ 188416                            (256)
#define SMEM_BYTES 188672

extern __shared__ unsigned char smem_raw[];

__global__ __launch_bounds__(256, 1)
void nms_loss_kernel(const int* __restrict__ pos_gt_index,
                     const float* __restrict__ gt_bboxes,
                     const float* __restrict__ bbox_preds,
                     float* __restrict__ out)
{
    float4*   sboxA   = (float4*)(smem_raw);
    float4*   sboxB   = (float4*)(smem_raw + 16384);
    unsigned* sadj    = (unsigned*)(smem_raw + 32768);
    float*    sgtiou  = (float*)(smem_raw + 163840);
    int*      skiller = (int*)(smem_raw + 180224);
    int*      snpush  = (int*)(smem_raw + 184320);
    int*      sfirst  = (int*)(smem_raw + 188416);

    __shared__ int   s_lastr;
    __shared__ float s_pull, s_push;
    __shared__ int   s_pcnt, s_qcnt;

    const int b = blockIdx.x;
    const int tid = threadIdx.x;

    // ---- setup (256 threads): permuted arrays by rank ----
    const float4* bp = (const float4*)(bbox_preds + (size_t)b * Nc * 4);
    for (int r = tid; r < Nc; r += 256) {
        int orig = g_perm[(b << 10) + r];
        float4 bx = bp[orig];
        sboxA[r] = bx;
        float area = (bx.z - bx.x + 1.0f) * (bx.w - bx.y + 1.0f);
        float sc = g_scores[(b << 10) + orig];
        int gi = pos_gt_index[b * Nc + orig];
        sboxB[r] = make_float4(area, sc, __int_as_float(gi), 0.0f);
        skiller[r] = -1;
        snpush[r] = 0;
    }
    const float4* gb = (const float4*)(gt_bboxes + (size_t)b * Gc * 4);
    for (int p = tid; p < Gc * Gc; p += 256) {
        int g1 = p >> 6, g2 = p & 63;
        float4 a = gb[g1];
        float4 c = gb[g2];
        float a1 = (a.z - a.x + 1.0f) * (a.w - a.y + 1.0f);
        float a2 = (c.z - c.x + 1.0f) * (c.w - c.y + 1.0f);
        sgtiou[p] = iou_legacy(a, c, a1, a2);
    }
    for (int g = tid; g < Gc; g += 256) sfirst[g] = 1 << 30;
    {
        const uint4* asrc = (const uint4*)(g_adj + ((size_t)b << 15));
        uint4* adst = (uint4*)sadj;
        for (int p = tid; p < (Nc * 32 / 4); p += 256) adst[p] = asrc[p];
    }
    if (tid == 0) { s_pull = 0.0f; s_push = 0.0f; s_pcnt = 0; s_qcnt = 0; }
    __syncthreads();

    // ---- Phase 1: bitwise NMS fixpoint, sequential rank order (warp 0) ----
    // rem: per-lane removed bits for ranks (lane<<5)|s. aj: uniform alive bits
    // of current word j (every lane tracks it via broadcast-LDS of row word j).
    if (tid < 32) {
        const int lane = tid;
        unsigned rem = 0u;
        int lastr = 0;
        #pragma unroll 1
        for (int j = 0; j < 32; j++) {
            unsigned aj = ~__shfl_sync(FULL, rem, j);   // once per word
            while (aj) {
                int s = __ffs(aj) - 1;
                int r = (j << 5) | s;
                lastr = r;
                int rowbase = r << 5;
                unsigned row_j = sadj[rowbase + j];      // uniform broadcast load
                unsigned row   = sadj[rowbase + lane];   // per-lane word
                aj &= ~row_j & ~(1u << s);               // critical chain
                unsigned kills = row & ~rem;             // off-chain bookkeeping
                rem |= row;
                if (lane == j) rem |= (1u << s);
                while (kills) {
                    int t = __ffs(kills) - 1;
                    kills &= kills - 1;
                    skiller[(lane << 5) | t] = r;
                }
            }
        }
        if (lane == 0) s_lastr = lastr;
    }
    __syncthreads();

    const int lastr = s_lastr;

    // ---- Phase 2a: first-kept-per-gt, push histogram, last-step liveness ----
    int pred_last = 0;
    for (int n = tid; n < Nc; n += 256) {
        int kr = skiller[n];
        if (kr < 0) {
            int g = __float_as_int(sboxB[n].z);
            atomicMin(&sfirst[g], n);
        } else {
            if (kr == lastr) pred_last = 1;
            int g = __float_as_int(sboxB[kr].z);
            int gn = __float_as_int(sboxB[n].z);
            if (gn != g) {
                float iouv = iou_legacy(sboxA[kr], sboxA[n], sboxB[kr].x, sboxB[n].x);
                if (iouv > sgtiou[(g << 6) + gn]) atomicAdd(&snpush[kr], 1);
            }
        }
    }
    int last_rem = __syncthreads_or(pred_last);   // barrier + OR

    // ---- Phase 2b: accumulate pull/push in parallel ----
    float lpull = 0.0f, lpush = 0.0f;
    int lpc = 0, lqc = 0;
    for (int n = tid; n < Nc; n += 256) {
        int kr = skiller[n];
        if (kr < 0) {
            int g = __float_as_int(sboxB[n].z);
            int prev = sfirst[g];
            if (prev < n) {
                lpc++;                                     // pcnt is ungated
                if (!(n == lastr && !last_rem)) {
                    float ms = fmaxf(iou_legacy(sboxA[prev], sboxA[n],
                                                sboxB[prev].x, sboxB[n].x), EPSf);
                    lpull += -__logf(1.0f - NMS_THRf + ms) * sboxB[n].y;
                }
            }
        } else {
            int g = __float_as_int(sboxB[kr].z);
            int gn = __float_as_int(sboxB[n].z);
            if (gn != g) {
                float iouv = iou_legacy(sboxA[kr], sboxA[n], sboxB[kr].x, sboxB[n].x);
                if (iouv > sgtiou[(g << 6) + gn]) {
                    lqc++;
                    lpush += -__logf(1.0f - iouv) * sboxB[n].y / (float)snpush[kr];
                }
            }
        }
    }
    #pragma unroll
    for (int off = 16; off > 0; off >>= 1) {
        lpull += __shfl_xor_sync(FULL, lpull, off);
        lpush += __shfl_xor_sync(FULL, lpush, off);
        lpc   += __shfl_xor_sync(FULL, lpc, off);
        lqc   += __shfl_xor_sync(FULL, lqc, off);
    }
    if ((tid & 31) == 0) {
        atomicAdd(&s_pull, lpull);
        atomicAdd(&s_push, lpush);
        atomicAdd(&s_pcnt, lpc);
        atomicAdd(&s_qcnt, lqc);
    }
    __syncthreads();

    // ---- finalize: last block sums per-batch partials ----
    if (tid == 0) {
        g_partial[b * 2 + 0] = s_push / ((float)s_qcnt + EPSf);
        g_partial[b * 2 + 1] = s_pull / ((float)s_pcnt + EPSf);
        __threadfence();
        int prev = atomicAdd(&g_done, 1);
        if (prev == Bc - 1) {
            float sp = 0.0f, sl = 0.0f;
            #pragma unroll
            for (int bb = 0; bb < Bc; bb++) {
                sp += *((volatile float*)&g_partial[bb * 2 + 0]);
                sl += *((volatile float*)&g_partial[bb * 2 + 1]);
            }
            out[0] = sp / (float)Bc;   // mean(push) * PUSH_W
            out[1] = sl / (float)Bc;   // mean(pull) * PULL_W
        }
    }
}

extern "C" void kernel_launch(void* const* d_in, const int* in_sizes, int n_in,
                              void* d_out, int out_size) {
    const int*   pos_inds     = (const int*)d_in[0];
    const int*   pos_gt_index = (const int*)d_in[1];
    const float* gt_bboxes    = (const float*)d_in[2];
    const float* bbox_preds   = (const float*)d_in[3];
    const float* cls_scores   = (const float*)d_in[4];
    const int*   gt_labels    = (const int*)d_in[5];
    float* out = (float*)d_out;

    cudaFuncSetAttribute(nms_loss_kernel,
                         cudaFuncAttributeMaxDynamicSharedMemorySize, SMEM_BYTES);

    gather_kernel<<<Bc, 256>>>(pos_inds, pos_gt_index, cls_scores, gt_labels);
    rank_kernel<<<dim3(128, Bc), 256>>>();
    adj_kernel<<<dim3(128, Bc), 256>>>(bbox_preds);
    nms_loss_kernel<<<Bc, 256, SMEM_BYTES>>>(pos_gt_index, gt_bboxes, bbox_preds, out);
}

// round 7
// speedup vs baseline: 48.4320x; 1.0158x over previous
#include <cuda_runtime.h>
#include <math.h>

#define Bc 8
#define Nc 1024
#define Mc 20000
#define Cc 80
#define Gc 64
#define NMS_THRf 0.5f
#define EPSf 1e-6f
#define FULL 0xffffffffu

// per-batch results: [b*2+0]=push_b, [b*2+1]=pull_b
__device__ float g_partial[Bc * 2];
__device__ int   g_done;
// adjacency bitmasks in RANK space: row r, word L, bit s <-> rank (L<<5)|s
__device__ unsigned g_adj[Bc * Nc * 32];
// gathered scores (original index space)
__device__ float g_scores[Bc * Nc];
// permutation: g_perm[b][rank] = original index
__device__ int g_perm[Bc * Nc];

__device__ __forceinline__ float iou_legacy(float4 a, float4 b, float area_a, float area_b) {
    float lx = fmaxf(a.x, b.x), ly = fmaxf(a.y, b.y);
    float rx = fminf(a.z, b.z), ry = fminf(a.w, b.w);
    float w = fmaxf(rx - lx + 1.0f, 0.0f), h = fmaxf(ry - ly + 1.0f, 0.0f);
    float ov = w * h;
    return ov / (area_a + area_b - ov);
}

// ---------------- score gather (also resets completion counter) ----------------
__global__ __launch_bounds__(256)
void gather_kernel(const int* __restrict__ pos_inds,
                   const int* __restrict__ pos_gt_index,
                   const float* __restrict__ cls_scores,
                   const int* __restrict__ gt_labels)
{
    const int b = blockIdx.x;
    if (b == 0 && threadIdx.x == 0) g_done = 0;
    for (int n = threadIdx.x; n < Nc; n += 256) {
        int gi = pos_gt_index[b * Nc + n];
        int lbl = gt_labels[b * Gc + gi];
        int pi = pos_inds[b * Nc + n];
        g_scores[(b << 10) + n] = cls_scores[((size_t)b * Mc + pi) * Cc + lbl];
    }
}

// ---------------- rank computation: 1 warp per row ----------------
__global__ __launch_bounds__(256)
void rank_kernel(void)
{
    __shared__ float ssc[Nc];
    const int b = blockIdx.y;
    for (int n = threadIdx.x; n < Nc; n += 256)
        ssc[n] = g_scores[(b << 10) + n];
    __syncthreads();

    const int wid = threadIdx.x >> 5, lane = threadIdx.x & 31;
    const int i = blockIdx.x * 8 + wid;
    const float si = ssc[i];
    int cnt = 0;
    #pragma unroll
    for (int w = 0; w < 32; w++) {
        int n = (w << 5) | lane;            // coalesced, conflict-free
        float sn = ssc[n];
        cnt += (sn > si) || (sn == si && n < i);
    }
    cnt = __reduce_add_sync(FULL, cnt);
    if (lane == 0) g_perm[(b << 10) + cnt] = i;   // unique ranks -> no conflicts
}

// ---------------- adjacency in rank space: 1 warp per row ----------------
__global__ __launch_bounds__(256)
void adj_kernel(const float* __restrict__ bbox_preds)
{
    __shared__ float4 sb[Nc];
    __shared__ float  sa[Nc];
    const int b = blockIdx.y;
    const float4* bp = (const float4*)(bbox_preds + (size_t)b * Nc * 4);
    for (int n = threadIdx.x; n < Nc; n += 256) {
        int orig = g_perm[(b << 10) + n];
        float4 bx = bp[orig];
        sb[n] = bx;
        sa[n] = (bx.z - bx.x + 1.0f) * (bx.w - bx.y + 1.0f);
    }
    __syncthreads();

    const int wid = threadIdx.x >> 5, lane = threadIdx.x & 31;
    const int i = blockIdx.x * 8 + wid;     // rank-space row
    const float4 bi = sb[i];
    const float ai = sa[i];
    unsigned myword = 0u;
    #pragma unroll
    for (int w = 0; w < 32; w++) {
        int n = (w << 5) | lane;            // coalesced, conflict-free
        float v = iou_legacy(bi, sb[n], ai, sa[n]);
        unsigned bal = __ballot_sync(FULL, v > NMS_THRf && n != i);
        if (w == lane) myword = bal;        // word L bit s <-> rank (L<<5)|s
    }
    g_adj[(((b << 10) + i) << 5) + lane] = myword;
}

// ---------------- fixpoint + parallel loss: 1 block per batch ----------------
// smem adjacency is bank-swizzled: word w of row r lives at sadj[r*32 + (w^(r&31))]
// dynamic smem layout (bytes):
//   sboxA   float4[1024] @ 0       box coords                (16384)
//   sboxB   float4[1024] @ 16384   (area, score, gt, -)      (16384)
//   sadj    u32[1024*32] @ 32768   swizzled                  (131072)
//   sgtiou  float[64*64] @ 163840                            (16384)
//   skiller int[1024]    @ 180224                            (4096)
//   snpush  int[1024]    @ 184320                            (4096)
//   sfirst  int[64]      @ 188416                            (256)
//   skept   u32[32]      @ 188672                            (128)
#define SMEM_BYTES 188800

extern __shared__ unsigned char smem_raw[];

__global__ __launch_bounds__(256, 1)
void nms_loss_kernel(const int* __restrict__ pos_gt_index,
                     const float* __restrict__ gt_bboxes,
                     const float* __restrict__ bbox_preds,
                     float* __restrict__ out)
{
    float4*   sboxA   = (float4*)(smem_raw);
    float4*   sboxB   = (float4*)(smem_raw + 16384);
    unsigned* sadj    = (unsigned*)(smem_raw + 32768);
    float*    sgtiou  = (float*)(smem_raw + 163840);
    int*      skiller = (int*)(smem_raw + 180224);
    int*      snpush  = (int*)(smem_raw + 184320);
    int*      sfirst  = (int*)(smem_raw + 188416);
    unsigned* skept   = (unsigned*)(smem_raw + 188672);

    __shared__ int   s_lastr;
    __shared__ float s_pull, s_push;
    __shared__ int   s_pcnt, s_qcnt;

    const int b = blockIdx.x;
    const int tid = threadIdx.x;

    // ---- setup (256 threads): permuted arrays by rank ----
    const float4* bp = (const float4*)(bbox_preds + (size_t)b * Nc * 4);
    for (int r = tid; r < Nc; r += 256) {
        int orig = g_perm[(b << 10) + r];
        float4 bx = bp[orig];
        sboxA[r] = bx;
        float area = (bx.z - bx.x + 1.0f) * (bx.w - bx.y + 1.0f);
        float sc = g_scores[(b << 10) + orig];
        int gi = pos_gt_index[b * Nc + orig];
        sboxB[r] = make_float4(area, sc, __int_as_float(gi), 0.0f);
        snpush[r] = 0;
    }
    const float4* gb = (const float4*)(gt_bboxes + (size_t)b * Gc * 4);
    for (int p = tid; p < Gc * Gc; p += 256) {
        int g1 = p >> 6, g2 = p & 63;
        float4 a = gb[g1];
        float4 c = gb[g2];
        float a1 = (a.z - a.x + 1.0f) * (a.w - a.y + 1.0f);
        float a2 = (c.z - c.x + 1.0f) * (c.w - c.y + 1.0f);
        sgtiou[p] = iou_legacy(a, c, a1, a2);
    }
    for (int g = tid; g < Gc; g += 256) sfirst[g] = 1 << 30;
    // swizzled copy of this batch's adjacency (128KB)
    {
        const uint4* asrc4 = (const uint4*)(g_adj + ((size_t)b << 15));
        for (int idx = tid; idx < Nc * 8; idx += 256) {
            uint4 v = asrc4[idx];
            int r = idx >> 3, w0 = (idx & 7) << 2, x = r & 31;
            int base = r << 5;
            sadj[base + ((w0 + 0) ^ x)] = v.x;
            sadj[base + ((w0 + 1) ^ x)] = v.y;
            sadj[base + ((w0 + 2) ^ x)] = v.z;
            sadj[base + ((w0 + 3) ^ x)] = v.w;
        }
    }
    if (tid == 0) { s_pull = 0.0f; s_push = 0.0f; s_pcnt = 0; s_qcnt = 0; }
    __syncthreads();

    // ---- Phase 1: branch-free bitwise NMS (warp 0), output = kept bitmask ----
    if (tid < 32) {
        const int lane = tid;
        unsigned rem = 0u;       // killed bits of group `lane` (from earlier pops)
        int lastr = 0;
        #pragma unroll 1
        for (int j = 0; j < 32; j++) {
            const int rb = j << 5;
            // intra-word adjacency: W[t] = word j of row (j*32+t); lane-invariant
            unsigned W[32];
            #pragma unroll
            for (int t = 0; t < 32; t++)
                W[t] = sadj[((rb | t) << 5) + (j ^ t)];
            unsigned aj = ~__shfl_sync(FULL, rem, j);   // alive bits of group j
            unsigned kept = 0u;
            #pragma unroll
            for (int s = 0; s < 32; s++) {
                unsigned m = (unsigned)(((int)(aj << (31 - s))) >> 31); // bcast bit s
                kept |= aj & (1u << s);
                aj = aj & ~(W[s] & m);                  // single LOP3 on chain
            }
            skept[j] = kept;                            // uniform value, same addr
            if (kept) lastr = rb | (31 - __clz(kept));
            // accumulate cross-word kills (uniform loop, conflict-free loads)
            unsigned kk = kept;
            while (kk) {
                int s = __ffs(kk) - 1;
                kk &= kk - 1;
                rem |= sadj[((rb | s) << 5) + (lane ^ s)];
            }
        }
        if (lane == 0) s_lastr = lastr;
    }
    __syncthreads();

    const int lastr = s_lastr;

    // ---- Phase 2a: recover killer(n) in parallel; first-kept-per-gt; histogram ----
    int pred_last = 0;
    for (int n = tid; n < Nc; n += 256) {
        int base = n << 5, x = n & 31;
        int kr = -1;
        #pragma unroll 1
        for (int w = 0; w < 32; w++) {
            unsigned m = sadj[base + (w ^ x)] & skept[w];  // bank = w^lane: clean
            if (m) { kr = (w << 5) | (__ffs(m) - 1); break; }
        }
        skiller[n] = kr;
        if (kr < 0) {
            int g = __float_as_int(sboxB[n].z);
            atomicMin(&sfirst[g], n);
        } else {
            if (kr == lastr) pred_last = 1;
            int g = __float_as_int(sboxB[kr].z);
            int gn = __float_as_int(sboxB[n].z);
            if (gn != g) {
                float iouv = iou_legacy(sboxA[kr], sboxA[n], sboxB[kr].x, sboxB[n].x);
                if (iouv > sgtiou[(g << 6) + gn]) atomicAdd(&snpush[kr], 1);
            }
        }
    }
    int last_rem = __syncthreads_or(pred_last);   // barrier + OR

    // ---- Phase 2b: accumulate pull/push in parallel ----
    float lpull = 0.0f, lpush = 0.0f;
    int lpc = 0, lqc = 0;
    for (int n = tid; n < Nc; n += 256) {
        int kr = skiller[n];
        if (kr < 0) {
            int g = __float_as_int(sboxB[n].z);
            int prev = sfirst[g];
            if (prev < n) {
                lpc++;                                     // pcnt is ungated
                if (!(n == lastr && !last_rem)) {
                    float ms = fmaxf(iou_legacy(sboxA[prev], sboxA[n],
                                                sboxB[prev].x, sboxB[n].x), EPSf);
                    lpull += -__logf(1.0f - NMS_THRf + ms) * sboxB[n].y;
                }
            }
        } else {
            int g = __float_as_int(sboxB[kr].z);
            int gn = __float_as_int(sboxB[n].z);
            if (gn != g) {
                float iouv = iou_legacy(sboxA[kr], sboxA[n], sboxB[kr].x, sboxB[n].x);
                if (iouv > sgtiou[(g << 6) + gn]) {
                    lqc++;
                    lpush += -__logf(1.0f - iouv) * sboxB[n].y / (float)snpush[kr];
                }
            }
        }
    }
    #pragma unroll
    for (int off = 16; off > 0; off >>= 1) {
        lpull += __shfl_xor_sync(FULL, lpull, off);
        lpush += __shfl_xor_sync(FULL, lpush, off);
        lpc   += __shfl_xor_sync(FULL, lpc, off);
        lqc   += __shfl_xor_sync(FULL, lqc, off);
    }
    if ((tid & 31) == 0) {
        atomicAdd(&s_pull, lpull);
        atomicAdd(&s_push, lpush);
        atomicAdd(&s_pcnt, lpc);
        atomicAdd(&s_qcnt, lqc);
    }
    __syncthreads();

    // ---- finalize: last block sums per-batch partials ----
    if (tid == 0) {
        g_partial[b * 2 + 0] = s_push / ((float)s_qcnt + EPSf);
        g_partial[b * 2 + 1] = s_pull / ((float)s_pcnt + EPSf);
        __threadfence();
        int prev = atomicAdd(&g_done, 1);
        if (prev == Bc - 1) {
            float sp = 0.0f, sl = 0.0f;
            #pragma unroll
            for (int bb = 0; bb < Bc; bb++) {
                sp += *((volatile float*)&g_partial[bb * 2 + 0]);
                sl += *((volatile float*)&g_partial[bb * 2 + 1]);
            }
            out[0] = sp / (float)Bc;   // mean(push) * PUSH_W
            out[1] = sl / (float)Bc;   // mean(pull) * PULL_W
        }
    }
}

extern "C" void kernel_launch(void* const* d_in, const int* in_sizes, int n_in,
                              void* d_out, int out_size) {
    const int*   pos_inds     = (const int*)d_in[0];
    const int*   pos_gt_index = (const int*)d_in[1];
    const float* gt_bboxes    = (const float*)d_in[2];
    const float* bbox_preds   = (const float*)d_in[3];
    const float* cls_scores   = (const float*)d_in[4];
    const int*   gt_labels    = (const int*)d_in[5];
    float* out = (float*)d_out;

    cudaFuncSetAttribute(nms_loss_kernel,
                         cudaFuncAttributeMaxDynamicSharedMemorySize, SMEM_BYTES);

    gather_kernel<<<Bc, 256>>>(pos_inds, pos_gt_index, cls_scores, gt_labels);
    rank_kernel<<<dim3(128, Bc), 256>>>();
    adj_kernel<<<dim3(128, Bc), 256>>>(bbox_preds);
    nms_loss_kernel<<<Bc, 256, SMEM_BYTES>>>(pos_gt_index, gt_bboxes, bbox_preds, out);
}

// round 8
// speedup vs baseline: 51.3249x; 1.0597x over previous
#include <cuda_runtime.h>
#include <math.h>

#define Bc 8
#define Nc 1024
#define Mc 20000
#define Cc 80
#define Gc 64
#define NMS_THRf 0.5f
#define EPSf 1e-6f
#define FULL 0xffffffffu

// per-batch results: [b*2+0]=push_b, [b*2+1]=pull_b
__device__ float g_partial[Bc * 2];
__device__ int   g_done;
// adjacency bitmasks in RANK space: row r, word L, bit s <-> rank (L<<5)|s
__device__ unsigned g_adj[Bc * Nc * 32];
// gathered scores (original index space)
__device__ float g_scores[Bc * Nc];
// permutation: g_perm[b][rank] = original index
__device__ int g_perm[Bc * Nc];

__device__ __forceinline__ float iou_legacy(float4 a, float4 b, float area_a, float area_b) {
    float lx = fmaxf(a.x, b.x), ly = fmaxf(a.y, b.y);
    float rx = fminf(a.z, b.z), ry = fminf(a.w, b.w);
    float w = fmaxf(rx - lx + 1.0f, 0.0f), h = fmaxf(ry - ly + 1.0f, 0.0f);
    float ov = w * h;
    return ov / (area_a + area_b - ov);
}

// ---------------- score gather (also resets completion counter) ----------------
__global__ __launch_bounds__(256)
void gather_kernel(const int* __restrict__ pos_inds,
                   const int* __restrict__ pos_gt_index,
                   const float* __restrict__ cls_scores,
                   const int* __restrict__ gt_labels)
{
    const int b = blockIdx.x;
    if (b == 0 && threadIdx.x == 0) g_done = 0;
    for (int n = threadIdx.x; n < Nc; n += 256) {
        int gi = pos_gt_index[b * Nc + n];
        int lbl = gt_labels[b * Gc + gi];
        int pi = pos_inds[b * Nc + n];
        g_scores[(b << 10) + n] = cls_scores[((size_t)b * Mc + pi) * Cc + lbl];
    }
}

// ---------------- rank computation: 1 warp per row ----------------
__global__ __launch_bounds__(256)
void rank_kernel(void)
{
    __shared__ float ssc[Nc];
    const int b = blockIdx.y;
    for (int n = threadIdx.x; n < Nc; n += 256)
        ssc[n] = g_scores[(b << 10) + n];
    __syncthreads();

    const int wid = threadIdx.x >> 5, lane = threadIdx.x & 31;
    const int i = blockIdx.x * 8 + wid;
    const float si = ssc[i];
    int cnt = 0;
    #pragma unroll
    for (int w = 0; w < 32; w++) {
        int n = (w << 5) | lane;            // coalesced, conflict-free
        float sn = ssc[n];
        cnt += (sn > si) || (sn == si && n < i);
    }
    cnt = __reduce_add_sync(FULL, cnt);
    if (lane == 0) g_perm[(b << 10) + cnt] = i;   // unique ranks -> no conflicts
}

// ---------------- adjacency in rank space: 1 warp per row ----------------
__global__ __launch_bounds__(256)
void adj_kernel(const float* __restrict__ bbox_preds)
{
    __shared__ float4 sb[Nc];
    __shared__ float  sa[Nc];
    const int b = blockIdx.y;
    const float4* bp = (const float4*)(bbox_preds + (size_t)b * Nc * 4);
    for (int n = threadIdx.x; n < Nc; n += 256) {
        int orig = g_perm[(b << 10) + n];
        float4 bx = bp[orig];
        sb[n] = bx;
        sa[n] = (bx.z - bx.x + 1.0f) * (bx.w - bx.y + 1.0f);
    }
    __syncthreads();

    const int wid = threadIdx.x >> 5, lane = threadIdx.x & 31;
    const int i = blockIdx.x * 8 + wid;     // rank-space row
    const float4 bi = sb[i];
    const float ai = sa[i];
    unsigned myword = 0u;
    #pragma unroll
    for (int w = 0; w < 32; w++) {
        int n = (w << 5) | lane;            // coalesced, conflict-free
        float v = iou_legacy(bi, sb[n], ai, sa[n]);
        unsigned bal = __ballot_sync(FULL, v > NMS_THRf && n != i);
        if (w == lane) myword = bal;        // word L bit s <-> rank (L<<5)|s
    }
    g_adj[(((b << 10) + i) << 5) + lane] = myword;
}

// ---------------- fixpoint + parallel loss: 1 block per batch ----------------
// smem adjacency is bank-swizzled: word w of row r lives at sadj[r*32 + (w^(r&31))]
// dynamic smem layout (bytes):
//   sboxA   float4[1024] @ 0       box coords                (16384)
//   sboxB   float4[1024] @ 16384   (area, score, gt, -)      (16384)
//   sadj    u32[1024*32] @ 32768   swizzled                  (131072)
//   sgtiou  float[64*64] @ 163840                            (16384)
//   skiller int[1024]    @ 180224                            (4096)
//   snpush  int[1024]    @ 184320                            (4096)
//   sfirst  int[64]      @ 188416                            (256)
//   skept   u32[32]      @ 188672                            (128)
#define SMEM_BYTES 188800

extern __shared__ unsigned char smem_raw[];

__global__ __launch_bounds__(256, 1)
void nms_loss_kernel(const int* __restrict__ pos_gt_index,
                     const float* __restrict__ gt_bboxes,
                     const float* __restrict__ bbox_preds,
                     float* __restrict__ out)
{
    float4*   sboxA   = (float4*)(smem_raw);
    float4*   sboxB   = (float4*)(smem_raw + 16384);
    unsigned* sadj    = (unsigned*)(smem_raw + 32768);
    float*    sgtiou  = (float*)(smem_raw + 163840);
    int*      skiller = (int*)(smem_raw + 180224);
    int*      snpush  = (int*)(smem_raw + 184320);
    int*      sfirst  = (int*)(smem_raw + 188416);
    unsigned* skept   = (unsigned*)(smem_raw + 188672);

    __shared__ int   s_lastr;
    __shared__ float s_pull, s_push;
    __shared__ int   s_pcnt, s_qcnt;

    const int b = blockIdx.x;
    const int tid = threadIdx.x;

    // ---- setup (256 threads): permuted arrays by rank ----
    const float4* bp = (const float4*)(bbox_preds + (size_t)b * Nc * 4);
    for (int r = tid; r < Nc; r += 256) {
        int orig = g_perm[(b << 10) + r];
        float4 bx = bp[orig];
        sboxA[r] = bx;
        float area = (bx.z - bx.x + 1.0f) * (bx.w - bx.y + 1.0f);
        float sc = g_scores[(b << 10) + orig];
        int gi = pos_gt_index[b * Nc + orig];
        sboxB[r] = make_float4(area, sc, __int_as_float(gi), 0.0f);
        snpush[r] = 0;
    }
    const float4* gb = (const float4*)(gt_bboxes + (size_t)b * Gc * 4);
    for (int p = tid; p < Gc * Gc; p += 256) {
        int g1 = p >> 6, g2 = p & 63;
        float4 a = gb[g1];
        float4 c = gb[g2];
        float a1 = (a.z - a.x + 1.0f) * (a.w - a.y + 1.0f);
        float a2 = (c.z - c.x + 1.0f) * (c.w - c.y + 1.0f);
        sgtiou[p] = iou_legacy(a, c, a1, a2);
    }
    for (int g = tid; g < Gc; g += 256) sfirst[g] = 1 << 30;
    // swizzled copy of this batch's adjacency (128KB)
    {
        const uint4* asrc4 = (const uint4*)(g_adj + ((size_t)b << 15));
        for (int idx = tid; idx < Nc * 8; idx += 256) {
            uint4 v = asrc4[idx];
            int r = idx >> 3, w0 = (idx & 7) << 2, x = r & 31;
            int base = r << 5;
            sadj[base + ((w0 + 0) ^ x)] = v.x;
            sadj[base + ((w0 + 1) ^ x)] = v.y;
            sadj[base + ((w0 + 2) ^ x)] = v.z;
            sadj[base + ((w0 + 3) ^ x)] = v.w;
        }
    }
    if (tid == 0) { s_pull = 0.0f; s_push = 0.0f; s_pcnt = 0; s_qcnt = 0; }
    __syncthreads();

    // ---- Phase 1: branch-free bitwise NMS (warp 0), no register arrays ----
    if (tid < 32) {
        const int lane = tid;
        unsigned rem = 0u;        // kills into group `lane` from kept rows so far
        unsigned mykept = 0u;     // kept word of group `lane`
        int lastr = 0;
        #pragma unroll 1
        for (int j = 0; j < 32; j++) {
            const int rb5 = j << 10;                    // ((j<<5)|s)<<5 base
            unsigned aj = ~__shfl_sync(FULL, rem, j);   // alive bits of group j
            // bit-serial suppression; kept bits stay set, so aj_final = kept.
            // LDS addresses depend only on (j,s): off-chain, pipelined by ptxas.
            #pragma unroll
            for (int s = 0; s < 32; s++) {
                unsigned m = (unsigned)(((int)(aj << (31 - s))) >> 31);
                aj &= ~(sadj[rb5 + (s << 5) + (j ^ s)] & m);
            }
            if (lane == j) mykept = aj;
            if (aj) lastr = (j << 5) | (31 - __clz(aj));
            // cross-word kill accumulation (uniform loop, conflict-free loads)
            unsigned kk = aj;
            while (kk) {
                int s = __ffs(kk) - 1;
                kk &= kk - 1;
                rem |= sadj[rb5 + (s << 5) + (lane ^ s)];
            }
        }
        skept[lane] = mykept;
        if (lane == 0) s_lastr = lastr;
    }
    __syncthreads();

    const int lastr = s_lastr;

    // ---- Phase 2a: recover killer(n) branchlessly; first-kept-per-gt; histogram ----
    int pred_last = 0;
    for (int n = tid; n < Nc; n += 256) {
        int base = n << 5, x = n & 31;
        unsigned nz = 0u;
        #pragma unroll
        for (int w = 0; w < 32; w++) {       // 32 independent conflict-free LDS
            unsigned m = sadj[base + (w ^ x)] & skept[w];
            nz |= (m != 0u) ? (1u << w) : 0u;
        }
        int kr = -1;
        if (nz) {
            int w = __ffs(nz) - 1;
            unsigned m = sadj[base + (w ^ x)] & skept[w];
            kr = (w << 5) | (__ffs(m) - 1);
        }
        skiller[n] = kr;
        if (kr < 0) {
            int g = __float_as_int(sboxB[n].z);
            atomicMin(&sfirst[g], n);
        } else {
            if (kr == lastr) pred_last = 1;
            int g = __float_as_int(sboxB[kr].z);
            int gn = __float_as_int(sboxB[n].z);
            if (gn != g) {
                float iouv = iou_legacy(sboxA[kr], sboxA[n], sboxB[kr].x, sboxB[n].x);
                if (iouv > sgtiou[(g << 6) + gn]) atomicAdd(&snpush[kr], 1);
            }
        }
    }
    int last_rem = __syncthreads_or(pred_last);   // barrier + OR

    // ---- Phase 2b: accumulate pull/push in parallel ----
    float lpull = 0.0f, lpush = 0.0f;
    int lpc = 0, lqc = 0;
    for (int n = tid; n < Nc; n += 256) {
        int kr = skiller[n];
        if (kr < 0) {
            int g = __float_as_int(sboxB[n].z);
            int prev = sfirst[g];
            if (prev < n) {
                lpc++;                                     // pcnt is ungated
                if (!(n == lastr && !last_rem)) {
                    float ms = fmaxf(iou_legacy(sboxA[prev], sboxA[n],
                                                sboxB[prev].x, sboxB[n].x), EPSf);
                    lpull += -__logf(1.0f - NMS_THRf + ms) * sboxB[n].y;
                }
            }
        } else {
            int g = __float_as_int(sboxB[kr].z);
            int gn = __float_as_int(sboxB[n].z);
            if (gn != g) {
                float iouv = iou_legacy(sboxA[kr], sboxA[n], sboxB[kr].x, sboxB[n].x);
                if (iouv > sgtiou[(g << 6) + gn]) {
                    lqc++;
                    lpush += -__logf(1.0f - iouv) * sboxB[n].y / (float)snpush[kr];
                }
            }
        }
    }
    #pragma unroll
    for (int off = 16; off > 0; off >>= 1) {
        lpull += __shfl_xor_sync(FULL, lpull, off);
        lpush += __shfl_xor_sync(FULL, lpush, off);
        lpc   += __shfl_xor_sync(FULL, lpc, off);
        lqc   += __shfl_xor_sync(FULL, lqc, off);
    }
    if ((tid & 31) == 0) {
        atomicAdd(&s_pull, lpull);
        atomicAdd(&s_push, lpush);
        atomicAdd(&s_pcnt, lpc);
        atomicAdd(&s_qcnt, lqc);
    }
    __syncthreads();

    // ---- finalize: last block sums per-batch partials ----
    if (tid == 0) {
        g_partial[b * 2 + 0] = s_push / ((float)s_qcnt + EPSf);
        g_partial[b * 2 + 1] = s_pull / ((float)s_pcnt + EPSf);
        __threadfence();
        int prev = atomicAdd(&g_done, 1);
        if (prev == Bc - 1) {
            float sp = 0.0f, sl = 0.0f;
            #pragma unroll
            for (int bb = 0; bb < Bc; bb++) {
                sp += *((volatile float*)&g_partial[bb * 2 + 0]);
                sl += *((volatile float*)&g_partial[bb * 2 + 1]);
            }
            out[0] = sp / (float)Bc;   // mean(push) * PUSH_W
            out[1] = sl / (float)Bc;   // mean(pull) * PULL_W
        }
    }
}

extern "C" void kernel_launch(void* const* d_in, const int* in_sizes, int n_in,
                              void* d_out, int out_size) {
    const int*   pos_inds     = (const int*)d_in[0];
    const int*   pos_gt_index = (const int*)d_in[1];
    const float* gt_bboxes    = (const float*)d_in[2];
    const float* bbox_preds   = (const float*)d_in[3];
    const float* cls_scores   = (const float*)d_in[4];
    const int*   gt_labels    = (const int*)d_in[5];
    float* out = (float*)d_out;

    cudaFuncSetAttribute(nms_loss_kernel,
                         cudaFuncAttributeMaxDynamicSharedMemorySize, SMEM_BYTES);

    gather_kernel<<<Bc, 256>>>(pos_inds, pos_gt_index, cls_scores, gt_labels);
    rank_kernel<<<dim3(128, Bc), 256>>>();
    adj_kernel<<<dim3(128, Bc), 256>>>(bbox_preds);
    nms_loss_kernel<<<Bc, 256, SMEM_BYTES>>>(pos_gt_index, gt_bboxes, bbox_preds, out);
}

// round 9
// speedup vs baseline: 96.3567x; 1.8774x over previous
#include <cuda_runtime.h>
#include <math.h>

#define Bc 8
#define Nc 1024
#define Mc 20000
#define Cc 80
#define Gc 64
#define NMS_THRf 0.5f
#define EPSf 1e-6f
#define FULL 0xffffffffu

// per-batch results: [b*2+0]=push_b, [b*2+1]=pull_b
__device__ float g_partial[Bc * 2];
__device__ int   g_done;
// adjacency bitmasks in RANK space: row r, word L, bit s <-> rank (L<<5)|s
__device__ unsigned g_adj[Bc * Nc * 32];
// gathered scores (original index space)
__device__ float g_scores[Bc * Nc];
// permutation: g_perm[b][rank] = original index
__device__ int g_perm[Bc * Nc];

__device__ __forceinline__ float iou_legacy(float4 a, float4 b, float area_a, float area_b) {
    float lx = fmaxf(a.x, b.x), ly = fmaxf(a.y, b.y);
    float rx = fminf(a.z, b.z), ry = fminf(a.w, b.w);
    float w = fmaxf(rx - lx + 1.0f, 0.0f), h = fmaxf(ry - ly + 1.0f, 0.0f);
    float ov = w * h;
    return ov / (area_a + area_b - ov);
}

// ---------------- score gather (also resets completion counter) ----------------
__global__ __launch_bounds__(256)
void gather_kernel(const int* __restrict__ pos_inds,
                   const int* __restrict__ pos_gt_index,
                   const float* __restrict__ cls_scores,
                   const int* __restrict__ gt_labels)
{
    const int b = blockIdx.x;
    if (b == 0 && threadIdx.x == 0) g_done = 0;
    for (int n = threadIdx.x; n < Nc; n += 256) {
        int gi = pos_gt_index[b * Nc + n];
        int lbl = gt_labels[b * Gc + gi];
        int pi = pos_inds[b * Nc + n];
        g_scores[(b << 10) + n] = cls_scores[((size_t)b * Mc + pi) * Cc + lbl];
    }
}

// ---------------- rank computation: 1 warp per row ----------------
__global__ __launch_bounds__(256)
void rank_kernel(void)
{
    __shared__ float ssc[Nc];
    const int b = blockIdx.y;
    for (int n = threadIdx.x; n < Nc; n += 256)
        ssc[n] = g_scores[(b << 10) + n];
    __syncthreads();

    const int wid = threadIdx.x >> 5, lane = threadIdx.x & 31;
    const int i = blockIdx.x * 8 + wid;
    const float si = ssc[i];
    int cnt = 0;
    #pragma unroll
    for (int w = 0; w < 32; w++) {
        int n = (w << 5) | lane;            // coalesced, conflict-free
        float sn = ssc[n];
        cnt += (sn > si) || (sn == si && n < i);
    }
    cnt = __reduce_add_sync(FULL, cnt);
    if (lane == 0) g_perm[(b << 10) + cnt] = i;   // unique ranks -> no conflicts
}

// ---------------- adjacency in rank space: 1 warp per row ----------------
__global__ __launch_bounds__(256)
void adj_kernel(const float* __restrict__ bbox_preds)
{
    __shared__ float4 sb[Nc];
    __shared__ float  sa[Nc];
    const int b = blockIdx.y;
    const float4* bp = (const float4*)(bbox_preds + (size_t)b * Nc * 4);
    for (int n = threadIdx.x; n < Nc; n += 256) {
        int orig = g_perm[(b << 10) + n];
        float4 bx = bp[orig];
        sb[n] = bx;
        sa[n] = (bx.z - bx.x + 1.0f) * (bx.w - bx.y + 1.0f);
    }
    __syncthreads();

    const int wid = threadIdx.x >> 5, lane = threadIdx.x & 31;
    const int i = blockIdx.x * 8 + wid;     // rank-space row
    const float4 bi = sb[i];
    const float ai = sa[i];
    unsigned myword = 0u;
    #pragma unroll
    for (int w = 0; w < 32; w++) {
        int n = (w << 5) | lane;            // coalesced, conflict-free
        float v = iou_legacy(bi, sb[n], ai, sa[n]);
        unsigned bal = __ballot_sync(FULL, v > NMS_THRf && n != i);
        if (w == lane) myword = bal;        // word L bit s <-> rank (L<<5)|s
    }
    g_adj[(((b << 10) + i) << 5) + lane] = myword;
}

// ---------------- fixpoint + parallel loss: 1 block per batch ----------------
// smem adjacency is bank-swizzled: word w of row r lives at sadj[r*32 + (w^(r&31))]
// dynamic smem layout (bytes):
//   sboxA   float4[1024] @ 0       box coords                (16384)
//   sboxB   float4[1024] @ 16384   (area, score, gt, -)      (16384)
//   sadj    u32[1024*32] @ 32768   swizzled                  (131072)
//   sgtiou  float[64*64] @ 163840                            (16384)
//   skiller int[1024]    @ 180224                            (4096)
//   snpush  int[1024]    @ 184320                            (4096)
//   sfirst  int[64]      @ 188416                            (256)
//   skeptM  u32[32]      @ 188672                            (128)
//   sdeadM  u32[32]      @ 188800                            (128)
#define SMEM_BYTES 188928

extern __shared__ unsigned char smem_raw[];

__global__ __launch_bounds__(256, 1)
void nms_loss_kernel(const int* __restrict__ pos_gt_index,
                     const float* __restrict__ gt_bboxes,
                     const float* __restrict__ bbox_preds,
                     float* __restrict__ out)
{
    float4*   sboxA   = (float4*)(smem_raw);
    float4*   sboxB   = (float4*)(smem_raw + 16384);
    unsigned* sadj    = (unsigned*)(smem_raw + 32768);
    float*    sgtiou  = (float*)(smem_raw + 163840);
    int*      skiller = (int*)(smem_raw + 180224);
    int*      snpush  = (int*)(smem_raw + 184320);
    int*      sfirst  = (int*)(smem_raw + 188416);
    unsigned* skeptM  = (unsigned*)(smem_raw + 188672);
    unsigned* sdeadM  = (unsigned*)(smem_raw + 188800);

    __shared__ int   s_lastr;
    __shared__ int   s_remaining;
    __shared__ float s_pull, s_push;
    __shared__ int   s_pcnt, s_qcnt;

    const int b = blockIdx.x;
    const int tid = threadIdx.x;

    // ---- setup (256 threads): permuted arrays by rank ----
    const float4* bp = (const float4*)(bbox_preds + (size_t)b * Nc * 4);
    for (int r = tid; r < Nc; r += 256) {
        int orig = g_perm[(b << 10) + r];
        float4 bx = bp[orig];
        sboxA[r] = bx;
        float area = (bx.z - bx.x + 1.0f) * (bx.w - bx.y + 1.0f);
        float sc = g_scores[(b << 10) + orig];
        int gi = pos_gt_index[b * Nc + orig];
        sboxB[r] = make_float4(area, sc, __int_as_float(gi), 0.0f);
        snpush[r] = 0;
    }
    const float4* gb = (const float4*)(gt_bboxes + (size_t)b * Gc * 4);
    for (int p = tid; p < Gc * Gc; p += 256) {
        int g1 = p >> 6, g2 = p & 63;
        float4 a = gb[g1];
        float4 c = gb[g2];
        float a1 = (a.z - a.x + 1.0f) * (a.w - a.y + 1.0f);
        float a2 = (c.z - c.x + 1.0f) * (c.w - c.y + 1.0f);
        sgtiou[p] = iou_legacy(a, c, a1, a2);
    }
    for (int g = tid; g < Gc; g += 256) sfirst[g] = 1 << 30;
    // swizzled copy of this batch's adjacency (128KB)
    {
        const uint4* asrc4 = (const uint4*)(g_adj + ((size_t)b << 15));
        for (int idx = tid; idx < Nc * 8; idx += 256) {
            uint4 v = asrc4[idx];
            int r = idx >> 3, w0 = (idx & 7) << 2, x = r & 31;
            int base = r << 5;
            sadj[base + ((w0 + 0) ^ x)] = v.x;
            sadj[base + ((w0 + 1) ^ x)] = v.y;
            sadj[base + ((w0 + 2) ^ x)] = v.z;
            sadj[base + ((w0 + 3) ^ x)] = v.w;
        }
    }
    if (tid < 32) { skeptM[tid] = 0u; sdeadM[tid] = 0u; }
    if (tid == 0) {
        s_pull = 0.0f; s_push = 0.0f; s_pcnt = 0; s_qcnt = 0;
        s_remaining = Nc;
    }
    __syncthreads();

    // ---- Phase 1: parallel-round NMS fixpoint (all 256 threads) ----
    // n DEAD  <=> some KEPT lower-rank neighbor
    // n KEPT  <=> all lower-rank neighbors DEAD
    // Monotone masks => stale intra-round reads are safe; the minimum
    // undecided row is always decidable => >=1 decision per round.
    {
        bool decided[4] = {false, false, false, false};
        while (true) {
            #pragma unroll
            for (int k = 0; k < 4; k++) {
                if (decided[k]) continue;
                int n = tid + (k << 8);
                int wn = n >> 5, sn = n & 31;
                int base = n << 5;
                unsigned dead_or = 0u, undec_or = 0u;
                for (int w = 0; w < wn; w++) {           // full lower words
                    unsigned r = sadj[base + (w ^ sn)];
                    unsigned kp = skeptM[w], dd = sdeadM[w];
                    dead_or  |= r & kp;
                    undec_or |= r & ~(kp | dd);
                }
                {                                         // partial word wn: bits < sn
                    unsigned r = sadj[base + (wn ^ sn)] & (sn ? ((1u << sn) - 1u) : 0u);
                    unsigned kp = skeptM[wn], dd = sdeadM[wn];
                    dead_or  |= r & kp;
                    undec_or |= r & ~(kp | dd);
                }
                if (dead_or) {
                    atomicOr(&sdeadM[wn], 1u << sn);
                    decided[k] = true;
                    atomicSub(&s_remaining, 1);
                } else if (!undec_or) {
                    atomicOr(&skeptM[wn], 1u << sn);
                    decided[k] = true;
                    atomicSub(&s_remaining, 1);
                }
            }
            __syncthreads();                 // round's mask writes visible
            int rem = s_remaining;           // no writes until after next barrier
            __syncthreads();                 // all reads done before next round
            if (rem == 0) break;
        }
    }
    if (tid == 0) {                          // lastr = highest-rank kept box
        int lastr = 0;
        for (int w = 31; w >= 0; w--) {
            if (skeptM[w]) { lastr = (w << 5) | (31 - __clz(skeptM[w])); break; }
        }
        s_lastr = lastr;
    }
    __syncthreads();

    const int lastr = s_lastr;

    // ---- Phase 2a: recover killer(n) branchlessly; first-kept-per-gt; histogram ----
    int pred_last = 0;
    for (int n = tid; n < Nc; n += 256) {
        int base = n << 5, x = n & 31;
        unsigned nz = 0u;
        #pragma unroll
        for (int w = 0; w < 32; w++) {       // 32 independent conflict-free LDS
            unsigned m = sadj[base + (w ^ x)] & skeptM[w];
            nz |= (m != 0u) ? (1u << w) : 0u;
        }
        int kr = -1;
        if (nz) {
            int w = __ffs(nz) - 1;
            unsigned m = sadj[base + (w ^ x)] & skeptM[w];
            kr = (w << 5) | (__ffs(m) - 1);
        }
        skiller[n] = kr;
        if (kr < 0) {
            int g = __float_as_int(sboxB[n].z);
            atomicMin(&sfirst[g], n);
        } else {
            if (kr == lastr) pred_last = 1;
            int g = __float_as_int(sboxB[kr].z);
            int gn = __float_as_int(sboxB[n].z);
            if (gn != g) {
                float iouv = iou_legacy(sboxA[kr], sboxA[n], sboxB[kr].x, sboxB[n].x);
                if (iouv > sgtiou[(g << 6) + gn]) atomicAdd(&snpush[kr], 1);
            }
        }
    }
    int last_rem = __syncthreads_or(pred_last);   // barrier + OR

    // ---- Phase 2b: accumulate pull/push in parallel ----
    float lpull = 0.0f, lpush = 0.0f;
    int lpc = 0, lqc = 0;
    for (int n = tid; n < Nc; n += 256) {
        int kr = skiller[n];
        if (kr < 0) {
            int g = __float_as_int(sboxB[n].z);
            int prev = sfirst[g];
            if (prev < n) {
                lpc++;                                     // pcnt is ungated
                if (!(n == lastr && !last_rem)) {
                    float ms = fmaxf(iou_legacy(sboxA[prev], sboxA[n],
                                                sboxB[prev].x, sboxB[n].x), EPSf);
                    lpull += -__logf(1.0f - NMS_THRf + ms) * sboxB[n].y;
                }
            }
        } else {
            int g = __float_as_int(sboxB[kr].z);
            int gn = __float_as_int(sboxB[n].z);
            if (gn != g) {
                float iouv = iou_legacy(sboxA[kr], sboxA[n], sboxB[kr].x, sboxB[n].x);
                if (iouv > sgtiou[(g << 6) + gn]) {
                    lqc++;
                    lpush += -__logf(1.0f - iouv) * sboxB[n].y / (float)snpush[kr];
                }
            }
        }
    }
    #pragma unroll
    for (int off = 16; off > 0; off >>= 1) {
        lpull += __shfl_xor_sync(FULL, lpull, off);
        lpush += __shfl_xor_sync(FULL, lpush, off);
        lpc   += __shfl_xor_sync(FULL, lpc, off);
        lqc   += __shfl_xor_sync(FULL, lqc, off);
    }
    if ((tid & 31) == 0) {
        atomicAdd(&s_pull, lpull);
        atomicAdd(&s_push, lpush);
        atomicAdd(&s_pcnt, lpc);
        atomicAdd(&s_qcnt, lqc);
    }
    __syncthreads();

    // ---- finalize: last block sums per-batch partials ----
    if (tid == 0) {
        g_partial[b * 2 + 0] = s_push / ((float)s_qcnt + EPSf);
        g_partial[b * 2 + 1] = s_pull / ((float)s_pcnt + EPSf);
        __threadfence();
        int prev = atomicAdd(&g_done, 1);
        if (prev == Bc - 1) {
            float sp = 0.0f, sl = 0.0f;
            #pragma unroll
            for (int bb = 0; bb < Bc; bb++) {
                sp += *((volatile float*)&g_partial[bb * 2 + 0]);
                sl += *((volatile float*)&g_partial[bb * 2 + 1]);
            }
            out[0] = sp / (float)Bc;   // mean(push) * PUSH_W
            out[1] = sl / (float)Bc;   // mean(pull) * PULL_W
        }
    }
}

extern "C" void kernel_launch(void* const* d_in, const int* in_sizes, int n_in,
                              void* d_out, int out_size) {
    const int*   pos_inds     = (const int*)d_in[0];
    const int*   pos_gt_index = (const int*)d_in[1];
    const float* gt_bboxes    = (const float*)d_in[2];
    const float* bbox_preds   = (const float*)d_in[3];
    const float* cls_scores   = (const float*)d_in[4];
    const int*   gt_labels    = (const int*)d_in[5];
    float* out = (float*)d_out;

    cudaFuncSetAttribute(nms_loss_kernel,
                         cudaFuncAttributeMaxDynamicSharedMemorySize, SMEM_BYTES);

    gather_kernel<<<Bc, 256>>>(pos_inds, pos_gt_index, cls_scores, gt_labels);
    rank_kernel<<<dim3(128, Bc), 256>>>();
    adj_kernel<<<dim3(128, Bc), 256>>>(bbox_preds);
    nms_loss_kernel<<<Bc, 256, SMEM_BYTES>>>(pos_gt_index, gt_bboxes, bbox_preds, out);
}

// round 10
// speedup vs baseline: 101.2214x; 1.0505x over previous
#include <cuda_runtime.h>
#include <math.h>

#define Bc 8
#define Nc 1024
#define Mc 20000
#define Cc 80
#define Gc 64
#define NMS_THRf 0.5f
#define EPSf 1e-6f
#define FULL 0xffffffffu

// per-batch results: [b*2+0]=push_b, [b*2+1]=pull_b
__device__ float g_partial[Bc * 2];
__device__ int   g_done;
// adjacency bitmasks in RANK space, LOWER TRIANGLE only:
// row r, words w <= r>>5 valid; word w bit s <-> rank (w<<5)|s
__device__ unsigned g_adj[Bc * Nc * 32];
// rank-permuted scores: g_scores[b][rank]
__device__ float g_scores[Bc * Nc];
// permutation: g_perm[b][rank] = original index
__device__ int g_perm[Bc * Nc];

__device__ __forceinline__ float iou_legacy(float4 a, float4 b, float area_a, float area_b) {
    float lx = fmaxf(a.x, b.x), ly = fmaxf(a.y, b.y);
    float rx = fminf(a.z, b.z), ry = fminf(a.w, b.w);
    float w = fmaxf(rx - lx + 1.0f, 0.0f), h = fmaxf(ry - ly + 1.0f, 0.0f);
    float ov = w * h;
    return ov / (area_a + area_b - ov);
}

// ---------------- fused gather + rank: 1 warp per row ----------------
__global__ __launch_bounds__(256)
void rank_kernel(const int* __restrict__ pos_inds,
                 const int* __restrict__ pos_gt_index,
                 const float* __restrict__ cls_scores,
                 const int* __restrict__ gt_labels)
{
    __shared__ float ssc[Nc];
    const int b = blockIdx.y;
    if (b == 0 && blockIdx.x == 0 && threadIdx.x == 0) g_done = 0;
    for (int n = threadIdx.x; n < Nc; n += 256) {
        int gi = pos_gt_index[b * Nc + n];
        int lbl = gt_labels[b * Gc + gi];
        int pi = pos_inds[b * Nc + n];
        ssc[n] = cls_scores[((size_t)b * Mc + pi) * Cc + lbl];
    }
    __syncthreads();

    const int wid = threadIdx.x >> 5, lane = threadIdx.x & 31;
    const int i = blockIdx.x * 8 + wid;
    const float si = ssc[i];
    int cnt = 0;
    #pragma unroll
    for (int w = 0; w < 32; w++) {
        int n = (w << 5) | lane;            // coalesced, conflict-free
        float sn = ssc[n];
        cnt += (sn > si) || (sn == si && n < i);
    }
    cnt = __reduce_add_sync(FULL, cnt);
    if (lane == 0) {
        g_perm[(b << 10) + cnt] = i;        // unique ranks -> no conflicts
        g_scores[(b << 10) + cnt] = si;     // rank-permuted scores
    }
}

// ---------------- lower-tri adjacency in rank space: 1 warp per row ----------------
__global__ __launch_bounds__(256)
void adj_kernel(const float* __restrict__ bbox_preds)
{
    __shared__ float4 sb[Nc];
    __shared__ float  sa[Nc];
    const int b = blockIdx.y;
    const float4* bp = (const float4*)(bbox_preds + (size_t)b * Nc * 4);
    for (int n = threadIdx.x; n < Nc; n += 256) {
        int orig = g_perm[(b << 10) + n];
        float4 bx = bp[orig];
        sb[n] = bx;
        sa[n] = (bx.z - bx.x + 1.0f) * (bx.w - bx.y + 1.0f);
    }
    __syncthreads();

    const int wid = threadIdx.x >> 5, lane = threadIdx.x & 31;
    const int i = blockIdx.x * 8 + wid;     // rank-space row
    const int wi = i >> 5;
    const float4 bi = sb[i];
    const float ai = sa[i];
    unsigned* dst = g_adj + ((((size_t)b << 10) + i) << 5);
    for (int w = 0; w <= wi; w++) {         // lower triangle only
        int n = (w << 5) | lane;            // coalesced, conflict-free
        float v = iou_legacy(bi, sb[n], ai, sa[n]);
        unsigned bal = __ballot_sync(FULL, v > NMS_THRf && n != i);
        if (lane == 0) dst[w] = bal;
    }
}

// ---------------- fixpoint + parallel loss: 1 block per batch ----------------
// smem adjacency is bank-swizzled: word w of row r lives at sadj[r*32 + (w^(r&31))]
// dynamic smem layout (bytes):
//   sboxA   float4[1024] @ 0       box coords                (16384)
//   sboxB   float4[1024] @ 16384   (area, score, gt, -)      (16384)
//   sadj    u32[1024*32] @ 32768   swizzled, lower-tri valid (131072)
//   sgtiou  float[64*64] @ 163840                            (16384)
//   skiller int[1024]    @ 180224                            (4096)
//   snpush  int[1024]    @ 184320                            (4096)
//   sfirst  int[64]      @ 188416                            (256)
//   skeptM  u32[32]      @ 188672                            (128)
//   sdeadM  u32[32]      @ 188800                            (128)
#define SMEM_BYTES 188928

extern __shared__ unsigned char smem_raw[];

__global__ __launch_bounds__(256, 1)
void nms_loss_kernel(const int* __restrict__ pos_gt_index,
                     const float* __restrict__ gt_bboxes,
                     const float* __restrict__ bbox_preds,
                     float* __restrict__ out)
{
    float4*   sboxA   = (float4*)(smem_raw);
    float4*   sboxB   = (float4*)(smem_raw + 16384);
    unsigned* sadj    = (unsigned*)(smem_raw + 32768);
    float*    sgtiou  = (float*)(smem_raw + 163840);
    int*      skiller = (int*)(smem_raw + 180224);
    int*      snpush  = (int*)(smem_raw + 184320);
    int*      sfirst  = (int*)(smem_raw + 188416);
    unsigned* skeptM  = (unsigned*)(smem_raw + 188672);
    unsigned* sdeadM  = (unsigned*)(smem_raw + 188800);

    __shared__ int   s_lastr;
    __shared__ int   s_remaining;
    __shared__ float s_pull, s_push;
    __shared__ int   s_pcnt, s_qcnt;

    const int b = blockIdx.x;
    const int tid = threadIdx.x;

    // ---- setup (256 threads): permuted arrays by rank ----
    const float4* bp = (const float4*)(bbox_preds + (size_t)b * Nc * 4);
    for (int r = tid; r < Nc; r += 256) {
        int orig = g_perm[(b << 10) + r];
        float4 bx = bp[orig];
        sboxA[r] = bx;
        float area = (bx.z - bx.x + 1.0f) * (bx.w - bx.y + 1.0f);
        float sc = g_scores[(b << 10) + r];           // rank-permuted already
        int gi = pos_gt_index[b * Nc + orig];
        sboxB[r] = make_float4(area, sc, __int_as_float(gi), 0.0f);
        snpush[r] = 0;
    }
    const float4* gb = (const float4*)(gt_bboxes + (size_t)b * Gc * 4);
    for (int p = tid; p < Gc * Gc; p += 256) {
        int g1 = p >> 6, g2 = p & 63;
        float4 a = gb[g1];
        float4 c = gb[g2];
        float a1 = (a.z - a.x + 1.0f) * (a.w - a.y + 1.0f);
        float a2 = (c.z - c.x + 1.0f) * (c.w - c.y + 1.0f);
        sgtiou[p] = iou_legacy(a, c, a1, a2);
    }
    for (int g = tid; g < Gc; g += 256) sfirst[g] = 1 << 30;
    // swizzled copy of lower-triangle adjacency (~66KB instead of 128KB)
    {
        const uint4* asrc4 = (const uint4*)(g_adj + ((size_t)b << 15));
        for (int idx = tid; idx < Nc * 8; idx += 256) {
            int r = idx >> 3, q = idx & 7;
            if ((q << 2) <= (r >> 5)) {                // quad overlaps lower tri
                uint4 v = asrc4[idx];
                int w0 = q << 2, x = r & 31;
                int base = r << 5;
                sadj[base + ((w0 + 0) ^ x)] = v.x;
                sadj[base + ((w0 + 1) ^ x)] = v.y;
                sadj[base + ((w0 + 2) ^ x)] = v.z;
                sadj[base + ((w0 + 3) ^ x)] = v.w;
            }
        }
    }
    if (tid < 32) { skeptM[tid] = 0u; sdeadM[tid] = 0u; }
    if (tid == 0) {
        s_pull = 0.0f; s_push = 0.0f; s_pcnt = 0; s_qcnt = 0;
        s_remaining = Nc;
    }
    __syncthreads();

    // ---- Phase 1: parallel-round NMS fixpoint (all 256 threads) ----
    // n DEAD  <=> some KEPT lower-rank neighbor
    // n KEPT  <=> all lower-rank neighbors DEAD
    {
        bool decided[4] = {false, false, false, false};
        while (true) {
            #pragma unroll
            for (int k = 0; k < 4; k++) {
                if (decided[k]) continue;
                int n = tid + (k << 8);
                int wn = n >> 5, sn = n & 31;
                int base = n << 5;
                unsigned dead_or = 0u, undec_or = 0u;
                for (int w = 0; w < wn; w++) {           // full lower words
                    unsigned r = sadj[base + (w ^ sn)];
                    unsigned kp = skeptM[w], dd = sdeadM[w];
                    dead_or  |= r & kp;
                    undec_or |= r & ~(kp | dd);
                }
                {                                         // partial word wn: bits < sn
                    unsigned r = sadj[base + (wn ^ sn)] & (sn ? ((1u << sn) - 1u) : 0u);
                    unsigned kp = skeptM[wn], dd = sdeadM[wn];
                    dead_or  |= r & kp;
                    undec_or |= r & ~(kp | dd);
                }
                if (dead_or) {
                    atomicOr(&sdeadM[wn], 1u << sn);
                    decided[k] = true;
                    atomicSub(&s_remaining, 1);
                } else if (!undec_or) {
                    atomicOr(&skeptM[wn], 1u << sn);
                    decided[k] = true;
                    atomicSub(&s_remaining, 1);
                }
            }
            __syncthreads();                 // round's mask writes visible
            int rem = s_remaining;           // no writes until after next barrier
            __syncthreads();                 // all reads done before next round
            if (rem == 0) break;
        }
    }
    if (tid == 0) {                          // lastr = highest-rank kept box
        int lastr = 0;
        for (int w = 31; w >= 0; w--) {
            if (skeptM[w]) { lastr = (w << 5) | (31 - __clz(skeptM[w])); break; }
        }
        s_lastr = lastr;
    }
    __syncthreads();

    const int lastr = s_lastr;

    // ---- Phase 2a: recover killer(n) (lower words only); per-gt first; histogram ----
    // killer(n) = lowest-rank kept neighbor, always < n for dead boxes; kept
    // boxes have no kept neighbors at all (independent set, symmetric adj).
    int pred_last = 0;
    for (int n = tid; n < Nc; n += 256) {
        int base = n << 5, x = n & 31, wn = n >> 5;
        unsigned nz = 0u;
        for (int w = 0; w <= wn; w++) {      // independent conflict-free LDS
            unsigned m = sadj[base + (w ^ x)] & skeptM[w];
            nz |= (m != 0u) ? (1u << w) : 0u;
        }
        int kr = -1;
        if (nz) {
            int w = __ffs(nz) - 1;
            unsigned m = sadj[base + (w ^ x)] & skeptM[w];
            kr = (w << 5) | (__ffs(m) - 1);
        }
        skiller[n] = kr;
        if (kr < 0) {
            int g = __float_as_int(sboxB[n].z);
            atomicMin(&sfirst[g], n);
        } else {
            if (kr == lastr) pred_last = 1;
            int g = __float_as_int(sboxB[kr].z);
            int gn = __float_as_int(sboxB[n].z);
            if (gn != g) {
                float iouv = iou_legacy(sboxA[kr], sboxA[n], sboxB[kr].x, sboxB[n].x);
                if (iouv > sgtiou[(g << 6) + gn]) atomicAdd(&snpush[kr], 1);
            }
        }
    }
    int last_rem = __syncthreads_or(pred_last);   // barrier + OR

    // ---- Phase 2b: accumulate pull/push in parallel ----
    float lpull = 0.0f, lpush = 0.0f;
    int lpc = 0, lqc = 0;
    for (int n = tid; n < Nc; n += 256) {
        int kr = skiller[n];
        if (kr < 0) {
            int g = __float_as_int(sboxB[n].z);
            int prev = sfirst[g];
            if (prev < n) {
                lpc++;                                     // pcnt is ungated
                if (!(n == lastr && !last_rem)) {
                    float ms = fmaxf(iou_legacy(sboxA[prev], sboxA[n],
                                                sboxB[prev].x, sboxB[n].x), EPSf);
                    lpull += -__logf(1.0f - NMS_THRf + ms) * sboxB[n].y;
                }
            }
        } else {
            int g = __float_as_int(sboxB[kr].z);
            int gn = __float_as_int(sboxB[n].z);
            if (gn != g) {
                float iouv = iou_legacy(sboxA[kr], sboxA[n], sboxB[kr].x, sboxB[n].x);
                if (iouv > sgtiou[(g << 6) + gn]) {
                    lqc++;
                    lpush += -__logf(1.0f - iouv) * sboxB[n].y / (float)snpush[kr];
                }
            }
        }
    }
    #pragma unroll
    for (int off = 16; off > 0; off >>= 1) {
        lpull += __shfl_xor_sync(FULL, lpull, off);
        lpush += __shfl_xor_sync(FULL, lpush, off);
        lpc   += __shfl_xor_sync(FULL, lpc, off);
        lqc   += __shfl_xor_sync(FULL, lqc, off);
    }
    if ((tid & 31) == 0) {
        atomicAdd(&s_pull, lpull);
        atomicAdd(&s_push, lpush);
        atomicAdd(&s_pcnt, lpc);
        atomicAdd(&s_qcnt, lqc);
    }
    __syncthreads();

    // ---- finalize: last block sums per-batch partials ----
    if (tid == 0) {
        g_partial[b * 2 + 0] = s_push / ((float)s_qcnt + EPSf);
        g_partial[b * 2 + 1] = s_pull / ((float)s_pcnt + EPSf);
        __threadfence();
        int prev = atomicAdd(&g_done, 1);
        if (prev == Bc - 1) {
            float sp = 0.0f, sl = 0.0f;
            #pragma unroll
            for (int bb = 0; bb < Bc; bb++) {
                sp += *((volatile float*)&g_partial[bb * 2 + 0]);
                sl += *((volatile float*)&g_partial[bb * 2 + 1]);
            }
            out[0] = sp / (float)Bc;   // mean(push) * PUSH_W
            out[1] = sl / (float)Bc;   // mean(pull) * PULL_W
        }
    }
}

extern "C" void kernel_launch(void* const* d_in, const int* in_sizes, int n_in,
                              void* d_out, int out_size) {
    const int*   pos_inds     = (const int*)d_in[0];
    const int*   pos_gt_index = (const int*)d_in[1];
    const float* gt_bboxes    = (const float*)d_in[2];
    const float* bbox_preds   = (const float*)d_in[3];
    const float* cls_scores   = (const float*)d_in[4];
    const int*   gt_labels    = (const int*)d_in[5];
    float* out = (float*)d_out;

    cudaFuncSetAttribute(nms_loss_kernel,
                         cudaFuncAttributeMaxDynamicSharedMemorySize, SMEM_BYTES);

    rank_kernel<<<dim3(128, Bc), 256>>>(pos_inds, pos_gt_index, cls_scores, gt_labels);
    adj_kernel<<<dim3(128, Bc), 256>>>(bbox_preds);
    nms_loss_kernel<<<Bc, 256, SMEM_BYTES>>>(pos_gt_index, gt_bboxes, bbox_preds, out);
}

// round 11
// speedup vs baseline: 105.0988x; 1.0383x over previous
#include <cuda_runtime.h>
#include <math.h>

#define Bc 8
#define Nc 1024
#define Mc 20000
#define Cc 80
#define Gc 64
#define NMS_THRf 0.5f
#define EPSf 1e-6f
#define FULL 0xffffffffu

#define NT 512      // nms_loss block size

// per-batch results: [b*2+0]=push_b, [b*2+1]=pull_b
__device__ float g_partial[Bc * 2];
__device__ int   g_done;
// adjacency bitmasks in RANK space, LOWER TRIANGLE only:
// row r, words w <= r>>5 valid; word w bit s <-> rank (w<<5)|s
__device__ unsigned g_adj[Bc * Nc * 32];
// rank-permuted scores: g_scores[b][rank]
__device__ float g_scores[Bc * Nc];
// permutation: g_perm[b][rank] = original index
__device__ int g_perm[Bc * Nc];

__device__ __forceinline__ float iou_legacy(float4 a, float4 b, float area_a, float area_b) {
    float lx = fmaxf(a.x, b.x), ly = fmaxf(a.y, b.y);
    float rx = fminf(a.z, b.z), ry = fminf(a.w, b.w);
    float w = fmaxf(rx - lx + 1.0f, 0.0f), h = fmaxf(ry - ly + 1.0f, 0.0f);
    float ov = w * h;
    return ov / (area_a + area_b - ov);
}

// ---------------- fused gather + rank: 32 rows per block, 4 rows per warp ----------------
__global__ __launch_bounds__(256)
void rank_kernel(const int* __restrict__ pos_inds,
                 const int* __restrict__ pos_gt_index,
                 const float* __restrict__ cls_scores,
                 const int* __restrict__ gt_labels)
{
    __shared__ float ssc[Nc];
    const int b = blockIdx.y;
    if (b == 0 && blockIdx.x == 0 && threadIdx.x == 0) g_done = 0;
    for (int n = threadIdx.x; n < Nc; n += 256) {
        int gi = pos_gt_index[b * Nc + n];
        int lbl = gt_labels[b * Gc + gi];
        int pi = pos_inds[b * Nc + n];
        ssc[n] = cls_scores[((size_t)b * Mc + pi) * Cc + lbl];
    }
    __syncthreads();

    const int wid = threadIdx.x >> 5, lane = threadIdx.x & 31;
    #pragma unroll
    for (int t = 0; t < 4; t++) {
        const int i = blockIdx.x * 32 + wid * 4 + t;
        const float si = ssc[i];
        int cnt = 0;
        #pragma unroll
        for (int w = 0; w < 32; w++) {
            int n = (w << 5) | lane;        // coalesced, conflict-free
            float sn = ssc[n];
            cnt += (sn > si) || (sn == si && n < i);
        }
        cnt = __reduce_add_sync(FULL, cnt);
        if (lane == 0) {
            g_perm[(b << 10) + cnt] = i;    // unique ranks -> no conflicts
            g_scores[(b << 10) + cnt] = si; // rank-permuted scores
        }
    }
}

// ---------------- lower-tri adjacency: 4 striped rows per warp ----------------
__global__ __launch_bounds__(256)
void adj_kernel(const float* __restrict__ bbox_preds)
{
    __shared__ float4 sb[Nc];
    __shared__ float  sa[Nc];
    const int b = blockIdx.y;
    const float4* bp = (const float4*)(bbox_preds + (size_t)b * Nc * 4);
    for (int n = threadIdx.x; n < Nc; n += 256) {
        int orig = g_perm[(b << 10) + n];
        float4 bx = bp[orig];
        sb[n] = bx;
        sa[n] = (bx.z - bx.x + 1.0f) * (bx.w - bx.y + 1.0f);
    }
    __syncthreads();

    const int wid = threadIdx.x >> 5, lane = threadIdx.x & 31;
    #pragma unroll
    for (int t = 0; t < 4; t++) {
        const int i = blockIdx.x * 8 + wid + (t << 8);   // striped rows: balance
        const int wi = i >> 5;
        const float4 bi = sb[i];
        const float ai = sa[i];
        unsigned* dst = g_adj + ((((size_t)b << 10) + i) << 5);
        for (int w = 0; w <= wi; w++) {     // lower triangle only
            int n = (w << 5) | lane;        // coalesced, conflict-free
            float v = iou_legacy(bi, sb[n], ai, sa[n]);
            unsigned bal = __ballot_sync(FULL, v > NMS_THRf && n != i);
            if (lane == 0) dst[w] = bal;
        }
    }
}

// ---------------- fixpoint + parallel loss: 1 block (512 thr) per batch ----------------
// smem adjacency is bank-swizzled: word w of row r lives at sadj[r*32 + (w^(r&31))]
// dynamic smem layout (bytes):
//   sboxA   float4[1024] @ 0       box coords                (16384)
//   sboxB   float4[1024] @ 16384   (area, score, gt, -)      (16384)
//   sadj    u32[1024*32] @ 32768   swizzled, lower-tri valid (131072)
//   sgtiou  float[64*64] @ 163840                            (16384)
//   skiller int[1024]    @ 180224                            (4096)
//   snpush  int[1024]    @ 184320                            (4096)
//   sfirst  int[64]      @ 188416                            (256)
//   skeptM  u32[32]      @ 188672                            (128)
//   sdeadM  u32[32]      @ 188800                            (128)
#define SMEM_BYTES 188928

extern __shared__ unsigned char smem_raw[];

__global__ __launch_bounds__(NT, 1)
void nms_loss_kernel(const int* __restrict__ pos_gt_index,
                     const float* __restrict__ gt_bboxes,
                     const float* __restrict__ bbox_preds,
                     float* __restrict__ out)
{
    float4*   sboxA   = (float4*)(smem_raw);
    float4*   sboxB   = (float4*)(smem_raw + 16384);
    unsigned* sadj    = (unsigned*)(smem_raw + 32768);
    float*    sgtiou  = (float*)(smem_raw + 163840);
    int*      skiller = (int*)(smem_raw + 180224);
    int*      snpush  = (int*)(smem_raw + 184320);
    int*      sfirst  = (int*)(smem_raw + 188416);
    unsigned* skeptM  = (unsigned*)(smem_raw + 188672);
    unsigned* sdeadM  = (unsigned*)(smem_raw + 188800);

    __shared__ int   s_lastr;
    __shared__ int   s_remaining;
    __shared__ float s_pull, s_push;
    __shared__ int   s_pcnt, s_qcnt;

    const int b = blockIdx.x;
    const int tid = threadIdx.x;

    // ---- setup: permuted arrays by rank ----
    const float4* bp = (const float4*)(bbox_preds + (size_t)b * Nc * 4);
    for (int r = tid; r < Nc; r += NT) {
        int orig = g_perm[(b << 10) + r];
        float4 bx = bp[orig];
        sboxA[r] = bx;
        float area = (bx.z - bx.x + 1.0f) * (bx.w - bx.y + 1.0f);
        float sc = g_scores[(b << 10) + r];           // rank-permuted already
        int gi = pos_gt_index[b * Nc + orig];
        sboxB[r] = make_float4(area, sc, __int_as_float(gi), 0.0f);
        snpush[r] = 0;
    }
    const float4* gb = (const float4*)(gt_bboxes + (size_t)b * Gc * 4);
    for (int p = tid; p < Gc * Gc; p += NT) {
        int g1 = p >> 6, g2 = p & 63;
        float4 a = gb[g1];
        float4 c = gb[g2];
        float a1 = (a.z - a.x + 1.0f) * (a.w - a.y + 1.0f);
        float a2 = (c.z - c.x + 1.0f) * (c.w - c.y + 1.0f);
        sgtiou[p] = iou_legacy(a, c, a1, a2);
    }
    for (int g = tid; g < Gc; g += NT) sfirst[g] = 1 << 30;
    // swizzled copy of lower-triangle adjacency (~66KB)
    {
        const uint4* asrc4 = (const uint4*)(g_adj + ((size_t)b << 15));
        for (int idx = tid; idx < Nc * 8; idx += NT) {
            int r = idx >> 3, q = idx & 7;
            if ((q << 2) <= (r >> 5)) {                // quad overlaps lower tri
                uint4 v = asrc4[idx];
                int w0 = q << 2, x = r & 31;
                int base = r << 5;
                sadj[base + ((w0 + 0) ^ x)] = v.x;
                sadj[base + ((w0 + 1) ^ x)] = v.y;
                sadj[base + ((w0 + 2) ^ x)] = v.z;
                sadj[base + ((w0 + 3) ^ x)] = v.w;
            }
        }
    }
    if (tid < 32) { skeptM[tid] = 0u; sdeadM[tid] = 0u; }
    if (tid == 0) {
        s_pull = 0.0f; s_push = 0.0f; s_pcnt = 0; s_qcnt = 0;
        s_remaining = Nc;
    }
    __syncthreads();

    // ---- Phase 1: parallel-round NMS fixpoint (all 512 threads, 2 items each) ----
    // n DEAD  <=> some KEPT lower-rank neighbor
    // n KEPT  <=> all lower-rank neighbors DEAD
    {
        bool decided[2] = {false, false};
        while (true) {
            #pragma unroll
            for (int k = 0; k < 2; k++) {
                if (decided[k]) continue;
                int n = tid + (k << 9);
                int wn = n >> 5, sn = n & 31;
                int base = n << 5;
                unsigned dead_or = 0u, undec_or = 0u;
                for (int w = 0; w < wn; w++) {           // full lower words
                    unsigned r = sadj[base + (w ^ sn)];
                    unsigned kp = skeptM[w], dd = sdeadM[w];
                    dead_or  |= r & kp;
                    undec_or |= r & ~(kp | dd);
                }
                {                                         // partial word wn: bits < sn
                    unsigned r = sadj[base + (wn ^ sn)] & (sn ? ((1u << sn) - 1u) : 0u);
                    unsigned kp = skeptM[wn], dd = sdeadM[wn];
                    dead_or  |= r & kp;
                    undec_or |= r & ~(kp | dd);
                }
                if (dead_or) {
                    atomicOr(&sdeadM[wn], 1u << sn);
                    decided[k] = true;
                    atomicSub(&s_remaining, 1);
                } else if (!undec_or) {
                    atomicOr(&skeptM[wn], 1u << sn);
                    decided[k] = true;
                    atomicSub(&s_remaining, 1);
                }
            }
            __syncthreads();                 // round's mask writes visible
            int rem = s_remaining;           // no writes until after next barrier
            __syncthreads();                 // all reads done before next round
            if (rem == 0) break;
        }
    }
    if (tid == 0) {                          // lastr = highest-rank kept box
        int lastr = 0;
        for (int w = 31; w >= 0; w--) {
            if (skeptM[w]) { lastr = (w << 5) | (31 - __clz(skeptM[w])); break; }
        }
        s_lastr = lastr;
    }
    __syncthreads();

    const int lastr = s_lastr;

    // ---- Phase 2a: recover killer(n) (lower words only); per-gt first; histogram ----
    // killer(n) = lowest-rank kept neighbor, always < n for dead boxes; kept
    // boxes have no kept neighbors at all (independent set, symmetric adj).
    int pred_last = 0;
    for (int n = tid; n < Nc; n += NT) {
        int base = n << 5, x = n & 31, wn = n >> 5;
        unsigned nz = 0u;
        for (int w = 0; w <= wn; w++) {      // independent conflict-free LDS
            unsigned m = sadj[base + (w ^ x)] & skeptM[w];
            nz |= (m != 0u) ? (1u << w) : 0u;
        }
        int kr = -1;
        if (nz) {
            int w = __ffs(nz) - 1;
            unsigned m = sadj[base + (w ^ x)] & skeptM[w];
            kr = (w << 5) | (__ffs(m) - 1);
        }
        skiller[n] = kr;
        if (kr < 0) {
            int g = __float_as_int(sboxB[n].z);
            atomicMin(&sfirst[g], n);
        } else {
            if (kr == lastr) pred_last = 1;
            int g = __float_as_int(sboxB[kr].z);
            int gn = __float_as_int(sboxB[n].z);
            if (gn != g) {
                float iouv = iou_legacy(sboxA[kr], sboxA[n], sboxB[kr].x, sboxB[n].x);
                if (iouv > sgtiou[(g << 6) + gn]) atomicAdd(&snpush[kr], 1);
            }
        }
    }
    int last_rem = __syncthreads_or(pred_last);   // barrier + OR

    // ---- Phase 2b: accumulate pull/push in parallel ----
    float lpull = 0.0f, lpush = 0.0f;
    int lpc = 0, lqc = 0;
    for (int n = tid; n < Nc; n += NT) {
        int kr = skiller[n];
        if (kr < 0) {
            int g = __float_as_int(sboxB[n].z);
            int prev = sfirst[g];
            if (prev < n) {
                lpc++;                                     // pcnt is ungated
                if (!(n == lastr && !last_rem)) {
                    float ms = fmaxf(iou_legacy(sboxA[prev], sboxA[n],
                                                sboxB[prev].x, sboxB[n].x), EPSf);
                    lpull += -__logf(1.0f - NMS_THRf + ms) * sboxB[n].y;
                }
            }
        } else {
            int g = __float_as_int(sboxB[kr].z);
            int gn = __float_as_int(sboxB[n].z);
            if (gn != g) {
                float iouv = iou_legacy(sboxA[kr], sboxA[n], sboxB[kr].x, sboxB[n].x);
                if (iouv > sgtiou[(g << 6) + gn]) {
                    lqc++;
                    lpush += -__logf(1.0f - iouv) * sboxB[n].y / (float)snpush[kr];
                }
            }
        }
    }
    #pragma unroll
    for (int off = 16; off > 0; off >>= 1) {
        lpull += __shfl_xor_sync(FULL, lpull, off);
        lpush += __shfl_xor_sync(FULL, lpush, off);
        lpc   += __shfl_xor_sync(FULL, lpc, off);
        lqc   += __shfl_xor_sync(FULL, lqc, off);
    }
    if ((tid & 31) == 0) {
        atomicAdd(&s_pull, lpull);
        atomicAdd(&s_push, lpush);
        atomicAdd(&s_pcnt, lpc);
        atomicAdd(&s_qcnt, lqc);
    }
    __syncthreads();

    // ---- finalize: last block sums per-batch partials ----
    if (tid == 0) {
        g_partial[b * 2 + 0] = s_push / ((float)s_qcnt + EPSf);
        g_partial[b * 2 + 1] = s_pull / ((float)s_pcnt + EPSf);
        __threadfence();
        int prev = atomicAdd(&g_done, 1);
        if (prev == Bc - 1) {
            float sp = 0.0f, sl = 0.0f;
            #pragma unroll
            for (int bb = 0; bb < Bc; bb++) {
                sp += *((volatile float*)&g_partial[bb * 2 + 0]);
                sl += *((volatile float*)&g_partial[bb * 2 + 1]);
            }
            out[0] = sp / (float)Bc;   // mean(push) * PUSH_W
            out[1] = sl / (float)Bc;   // mean(pull) * PULL_W
        }
    }
}

extern "C" void kernel_launch(void* const* d_in, const int* in_sizes, int n_in,
                              void* d_out, int out_size) {
    const int*   pos_inds     = (const int*)d_in[0];
    const int*   pos_gt_index = (const int*)d_in[1];
    const float* gt_bboxes    = (const float*)d_in[2];
    const float* bbox_preds   = (const float*)d_in[3];
    const float* cls_scores   = (const float*)d_in[4];
    const int*   gt_labels    = (const int*)d_in[5];
    float* out = (float*)d_out;

    cudaFuncSetAttribute(nms_loss_kernel,
                         cudaFuncAttributeMaxDynamicSharedMemorySize, SMEM_BYTES);

    rank_kernel<<<dim3(32, Bc), 256>>>(pos_inds, pos_gt_index, cls_scores, gt_labels);
    adj_kernel<<<dim3(32, Bc), 256>>>(bbox_preds);
    nms_loss_kernel<<<Bc, NT, SMEM_BYTES>>>(pos_gt_index, gt_bboxes, bbox_preds, out);
}

// round 12
// speedup vs baseline: 106.0251x; 1.0088x over previous
#include <cuda_runtime.h>
#include <math.h>

#define Bc 8
#define Nc 1024
#define Mc 20000
#define Cc 80
#define Gc 64
#define NMS_THRf 0.5f
#define EPSf 1e-6f
#define FULL 0xffffffffu

#define NT 512      // nms_loss block size

// per-batch results: [b*2+0]=push_b, [b*2+1]=pull_b
__device__ float g_partial[Bc * 2];
__device__ int   g_done;
// adjacency bitmasks in RANK space, LOWER TRIANGLE only:
// row r, words w <= r>>5 valid; word w bit s <-> rank (w<<5)|s
__device__ unsigned g_adj[Bc * Nc * 32];
// gathered scores in ORIGINAL index space (linear)
__device__ float g_scores_orig[Bc * Nc];
// rank-permuted scores: g_scores[b][rank]
__device__ float g_scores[Bc * Nc];
// permutation: g_perm[b][rank] = original index
__device__ int g_perm[Bc * Nc];

__device__ __forceinline__ float iou_legacy(float4 a, float4 b, float area_a, float area_b) {
    float lx = fmaxf(a.x, b.x), ly = fmaxf(a.y, b.y);
    float rx = fminf(a.z, b.z), ry = fminf(a.w, b.w);
    float w = fmaxf(rx - lx + 1.0f, 0.0f), h = fmaxf(ry - ly + 1.0f, 0.0f);
    float ov = w * h;
    return ov / (area_a + area_b - ov);
}

// ---------------- score gather: one pass, high MLP ----------------
__global__ __launch_bounds__(256)
void gather_kernel(const int* __restrict__ pos_inds,
                   const int* __restrict__ pos_gt_index,
                   const float* __restrict__ cls_scores,
                   const int* __restrict__ gt_labels)
{
    const int b = blockIdx.x;
    const int tid = threadIdx.x;
    if (b == 0 && tid == 0) g_done = 0;
    // 4 items/thread; all index loads issued up-front (independent)
    int pi[4], gi[4];
    #pragma unroll
    for (int k = 0; k < 4; k++) {
        int n = tid + (k << 8);
        pi[k] = pos_inds[b * Nc + n];
        gi[k] = pos_gt_index[b * Nc + n];
    }
    int lbl[4];
    #pragma unroll
    for (int k = 0; k < 4; k++) lbl[k] = gt_labels[b * Gc + gi[k]];
    #pragma unroll
    for (int k = 0; k < 4; k++) {
        int n = tid + (k << 8);
        g_scores_orig[(b << 10) + n] =
            cls_scores[((size_t)b * Mc + pi[k]) * Cc + lbl[k]];
    }
}

// ---------------- rank: 32 rows per block, 4 rows per warp ----------------
__global__ __launch_bounds__(256)
void rank_kernel(void)
{
    __shared__ float ssc[Nc];
    const int b = blockIdx.y;
    // coalesced, L2-hot fill
    {
        const float4* src = (const float4*)(g_scores_orig + (b << 10));
        float4* dst = (float4*)ssc;
        for (int p = threadIdx.x; p < Nc / 4; p += 256) dst[p] = src[p];
    }
    __syncthreads();

    const int wid = threadIdx.x >> 5, lane = threadIdx.x & 31;
    #pragma unroll
    for (int t = 0; t < 4; t++) {
        const int i = blockIdx.x * 32 + wid * 4 + t;
        const float si = ssc[i];
        int cnt = 0;
        #pragma unroll
        for (int w = 0; w < 32; w++) {
            int n = (w << 5) | lane;        // coalesced, conflict-free
            float sn = ssc[n];
            cnt += (sn > si) || (sn == si && n < i);
        }
        cnt = __reduce_add_sync(FULL, cnt);
        if (lane == 0) {
            g_perm[(b << 10) + cnt] = i;    // unique ranks -> no conflicts
            g_scores[(b << 10) + cnt] = si; // rank-permuted scores
        }
    }
}

// ---------------- lower-tri adjacency: 4 striped rows per warp ----------------
__global__ __launch_bounds__(256)
void adj_kernel(const float* __restrict__ bbox_preds)
{
    __shared__ float4 sb[Nc];
    __shared__ float  sa[Nc];
    const int b = blockIdx.y;
    const float4* bp = (const float4*)(bbox_preds + (size_t)b * Nc * 4);
    for (int n = threadIdx.x; n < Nc; n += 256) {
        int orig = g_perm[(b << 10) + n];
        float4 bx = bp[orig];
        sb[n] = bx;
        sa[n] = (bx.z - bx.x + 1.0f) * (bx.w - bx.y + 1.0f);
    }
    __syncthreads();

    const int wid = threadIdx.x >> 5, lane = threadIdx.x & 31;
    #pragma unroll
    for (int t = 0; t < 4; t++) {
        const int i = blockIdx.x * 8 + wid + (t << 8);   // striped rows: balance
        const int wi = i >> 5;
        const float4 bi = sb[i];
        const float ai = sa[i];
        unsigned* dst = g_adj + ((((size_t)b << 10) + i) << 5);
        for (int w = 0; w <= wi; w++) {     // lower triangle only
            int n = (w << 5) | lane;        // coalesced, conflict-free
            float v = iou_legacy(bi, sb[n], ai, sa[n]);
            unsigned bal = __ballot_sync(FULL, v > NMS_THRf && n != i);
            if (lane == 0) dst[w] = bal;
        }
    }
}

// ---------------- fixpoint + parallel loss: 1 block (512 thr) per batch ----------------
// smem adjacency is bank-swizzled: word w of row r lives at sadj[r*32 + (w^(r&31))]
// dynamic smem layout (bytes):
//   sboxA   float4[1024] @ 0       box coords                (16384)
//   sboxB   float4[1024] @ 16384   (area, score, gt, -)      (16384)
//   sadj    u32[1024*32] @ 32768   swizzled, lower-tri valid (131072)
//   sgtiou  float[64*64] @ 163840                            (16384)
//   skiller int[1024]    @ 180224                            (4096)
//   snpush  int[1024]    @ 184320                            (4096)
//   sfirst  int[64]      @ 188416                            (256)
//   skeptM  u32[32]      @ 188672                            (128)
//   sdeadM  u32[32]      @ 188800                            (128)
#define SMEM_BYTES 188928

extern __shared__ unsigned char smem_raw[];

__global__ __launch_bounds__(NT, 1)
void nms_loss_kernel(const int* __restrict__ pos_gt_index,
                     const float* __restrict__ gt_bboxes,
                     const float* __restrict__ bbox_preds,
                     float* __restrict__ out)
{
    float4*   sboxA   = (float4*)(smem_raw);
    float4*   sboxB   = (float4*)(smem_raw + 16384);
    unsigned* sadj    = (unsigned*)(smem_raw + 32768);
    float*    sgtiou  = (float*)(smem_raw + 163840);
    int*      skiller = (int*)(smem_raw + 180224);
    int*      snpush  = (int*)(smem_raw + 184320);
    int*      sfirst  = (int*)(smem_raw + 188416);
    unsigned* skeptM  = (unsigned*)(smem_raw + 188672);
    unsigned* sdeadM  = (unsigned*)(smem_raw + 188800);

    __shared__ int   s_lastr;
    __shared__ int   s_remaining;
    __shared__ float s_pull, s_push;
    __shared__ int   s_pcnt, s_qcnt;

    const int b = blockIdx.x;
    const int tid = threadIdx.x;

    // ---- setup: permuted arrays by rank ----
    const float4* bp = (const float4*)(bbox_preds + (size_t)b * Nc * 4);
    for (int r = tid; r < Nc; r += NT) {
        int orig = g_perm[(b << 10) + r];
        float4 bx = bp[orig];
        sboxA[r] = bx;
        float area = (bx.z - bx.x + 1.0f) * (bx.w - bx.y + 1.0f);
        float sc = g_scores[(b << 10) + r];           // rank-permuted already
        int gi = pos_gt_index[b * Nc + orig];
        sboxB[r] = make_float4(area, sc, __int_as_float(gi), 0.0f);
        snpush[r] = 0;
    }
    const float4* gb = (const float4*)(gt_bboxes + (size_t)b * Gc * 4);
    for (int p = tid; p < Gc * Gc; p += NT) {
        int g1 = p >> 6, g2 = p & 63;
        float4 a = gb[g1];
        float4 c = gb[g2];
        float a1 = (a.z - a.x + 1.0f) * (a.w - a.y + 1.0f);
        float a2 = (c.z - c.x + 1.0f) * (c.w - c.y + 1.0f);
        sgtiou[p] = iou_legacy(a, c, a1, a2);
    }
    for (int g = tid; g < Gc; g += NT) sfirst[g] = 1 << 30;
    // swizzled copy of lower-triangle adjacency (~66KB)
    {
        const uint4* asrc4 = (const uint4*)(g_adj + ((size_t)b << 15));
        for (int idx = tid; idx < Nc * 8; idx += NT) {
            int r = idx >> 3, q = idx & 7;
            if ((q << 2) <= (r >> 5)) {                // quad overlaps lower tri
                uint4 v = asrc4[idx];
                int w0 = q << 2, x = r & 31;
                int base = r << 5;
                sadj[base + ((w0 + 0) ^ x)] = v.x;
                sadj[base + ((w0 + 1) ^ x)] = v.y;
                sadj[base + ((w0 + 2) ^ x)] = v.z;
                sadj[base + ((w0 + 3) ^ x)] = v.w;
            }
        }
    }
    if (tid < 32) { skeptM[tid] = 0u; sdeadM[tid] = 0u; }
    if (tid == 0) {
        s_pull = 0.0f; s_push = 0.0f; s_pcnt = 0; s_qcnt = 0;
        s_remaining = Nc;
    }
    __syncthreads();

    // ---- Phase 1: parallel-round NMS fixpoint (512 threads, 2 items each) ----
    // n DEAD  <=> some KEPT lower-rank neighbor
    // n KEPT  <=> all lower-rank neighbors DEAD
    {
        bool decided[2] = {false, false};
        while (true) {
            #pragma unroll
            for (int k = 0; k < 2; k++) {
                if (decided[k]) continue;
                int n = tid + (k << 9);
                int wn = n >> 5, sn = n & 31;
                int base = n << 5;
                unsigned dead_or = 0u, undec_or = 0u;
                for (int w = 0; w < wn; w++) {           // full lower words
                    unsigned r = sadj[base + (w ^ sn)];
                    unsigned kp = skeptM[w], dd = sdeadM[w];
                    dead_or  |= r & kp;
                    undec_or |= r & ~(kp | dd);
                }
                {                                         // partial word wn: bits < sn
                    unsigned r = sadj[base + (wn ^ sn)] & (sn ? ((1u << sn) - 1u) : 0u);
                    unsigned kp = skeptM[wn], dd = sdeadM[wn];
                    dead_or  |= r & kp;
                    undec_or |= r & ~(kp | dd);
                }
                if (dead_or) {
                    atomicOr(&sdeadM[wn], 1u << sn);
                    decided[k] = true;
                    atomicSub(&s_remaining, 1);
                } else if (!undec_or) {
                    atomicOr(&skeptM[wn], 1u << sn);
                    decided[k] = true;
                    atomicSub(&s_remaining, 1);
                }
            }
            __syncthreads();                 // round's mask writes visible
            int rem = s_remaining;           // no writes until after next barrier
            __syncthreads();                 // all reads done before next round
            if (rem == 0) break;
        }
    }
    if (tid == 0) {                          // lastr = highest-rank kept box
        int lastr = 0;
        for (int w = 31; w >= 0; w--) {
            if (skeptM[w]) { lastr = (w << 5) | (31 - __clz(skeptM[w])); break; }
        }
        s_lastr = lastr;
    }
    __syncthreads();

    const int lastr = s_lastr;

    // ---- Phase 2a: recover killer(n) (lower words only); per-gt first; histogram ----
    // killer(n) = lowest-rank kept neighbor, always < n for dead boxes; kept
    // boxes have no kept neighbors at all (independent set, symmetric adj).
    int pred_last = 0;
    for (int n = tid; n < Nc; n += NT) {
        int base = n << 5, x = n & 31, wn = n >> 5;
        unsigned nz = 0u;
        for (int w = 0; w <= wn; w++) {      // independent conflict-free LDS
            unsigned m = sadj[base + (w ^ x)] & skeptM[w];
            nz |= (m != 0u) ? (1u << w) : 0u;
        }
        int kr = -1;
        if (nz) {
            int w = __ffs(nz) - 1;
            unsigned m = sadj[base + (w ^ x)] & skeptM[w];
            kr = (w << 5) | (__ffs(m) - 1);
        }
        skiller[n] = kr;
        if (kr < 0) {
            int g = __float_as_int(sboxB[n].z);
            atomicMin(&sfirst[g], n);
        } else {
            if (kr == lastr) pred_last = 1;
            int g = __float_as_int(sboxB[kr].z);
            int gn = __float_as_int(sboxB[n].z);
            if (gn != g) {
                float iouv = iou_legacy(sboxA[kr], sboxA[n], sboxB[kr].x, sboxB[n].x);
                if (iouv > sgtiou[(g << 6) + gn]) atomicAdd(&snpush[kr], 1);
            }
        }
    }
    int last_rem = __syncthreads_or(pred_last);   // barrier + OR

    // ---- Phase 2b: accumulate pull/push in parallel ----
    float lpull = 0.0f, lpush = 0.0f;
    int lpc = 0, lqc = 0;
    for (int n = tid; n < Nc; n += NT) {
        int kr = skiller[n];
        if (kr < 0) {
            int g = __float_as_int(sboxB[n].z);
            int prev = sfirst[g];
            if (prev < n) {
                lpc++;                                     // pcnt is ungated
                if (!(n == lastr && !last_rem)) {
                    float ms = fmaxf(iou_legacy(sboxA[prev], sboxA[n],
                                                sboxB[prev].x, sboxB[n].x), EPSf);
                    lpull += -__logf(1.0f - NMS_THRf + ms) * sboxB[n].y;
                }
            }
        } else {
            int g = __float_as_int(sboxB[kr].z);
            int gn = __float_as_int(sboxB[n].z);
            if (gn != g) {
                float iouv = iou_legacy(sboxA[kr], sboxA[n], sboxB[kr].x, sboxB[n].x);
                if (iouv > sgtiou[(g << 6) + gn]) {
                    lqc++;
                    lpush += -__logf(1.0f - iouv) * sboxB[n].y / (float)snpush[kr];
                }
            }
        }
    }
    #pragma unroll
    for (int off = 16; off > 0; off >>= 1) {
        lpull += __shfl_xor_sync(FULL, lpull, off);
        lpush += __shfl_xor_sync(FULL, lpush, off);
        lpc   += __shfl_xor_sync(FULL, lpc, off);
        lqc   += __shfl_xor_sync(FULL, lqc, off);
    }
    if ((tid & 31) == 0) {
        atomicAdd(&s_pull, lpull);
        atomicAdd(&s_push, lpush);
        atomicAdd(&s_pcnt, lpc);
        atomicAdd(&s_qcnt, lqc);
    }
    __syncthreads();

    // ---- finalize: last block sums per-batch partials ----
    if (tid == 0) {
        g_partial[b * 2 + 0] = s_push / ((float)s_qcnt + EPSf);
        g_partial[b * 2 + 1] = s_pull / ((float)s_pcnt + EPSf);
        __threadfence();
        int prev = atomicAdd(&g_done, 1);
        if (prev == Bc - 1) {
            float sp = 0.0f, sl = 0.0f;
            #pragma unroll
            for (int bb = 0; bb < Bc; bb++) {
                sp += *((volatile float*)&g_partial[bb * 2 + 0]);
                sl += *((volatile float*)&g_partial[bb * 2 + 1]);
            }
            out[0] = sp / (float)Bc;   // mean(push) * PUSH_W
            out[1] = sl / (float)Bc;   // mean(pull) * PULL_W
        }
    }
}

extern "C" void kernel_launch(void* const* d_in, const int* in_sizes, int n_in,
                              void* d_out, int out_size) {
    const int*   pos_inds     = (const int*)d_in[0];
    const int*   pos_gt_index = (const int*)d_in[1];
    const float* gt_bboxes    = (const float*)d_in[2];
    const float* bbox_preds   = (const float*)d_in[3];
    const float* cls_scores   = (const float*)d_in[4];
    const int*   gt_labels    = (const int*)d_in[5];
    float* out = (float*)d_out;

    cudaFuncSetAttribute(nms_loss_kernel,
                         cudaFuncAttributeMaxDynamicSharedMemorySize, SMEM_BYTES);

    gather_kernel<<<Bc, 256>>>(pos_inds, pos_gt_index, cls_scores, gt_labels);
    rank_kernel<<<dim3(32, Bc), 256>>>();
    adj_kernel<<<dim3(32, Bc), 256>>>(bbox_preds);
    nms_loss_kernel<<<Bc, NT, SMEM_BYTES>>>(pos_gt_index, gt_bboxes, bbox_preds, out);
}